// round 1
// baseline (speedup 1.0000x reference)
#include <cuda_runtime.h>
#include <math.h>
#include <stdint.h>

#define N_NODES 50000
#define N_EDGES 800000
#define DIM 128

// ---------------- scratch (static device allocations) ----------------
__device__ float g_agg[(size_t)N_NODES * DIM * 2];   // interleaved (sum_exp, sum_msg_exp)
__device__ float g_h1[(size_t)N_NODES * 256];        // h @ W1.T
__device__ float g_PQ[(size_t)N_NODES * 256];        // [P | Q] per node
__device__ float g_bnsum[512];                       // col sums / sumsq
__device__ float g_bnstat[512];                      // fused scale / bias

// ---------------- kernel 1: edge message + scatter softmax accumulation ----------------
__global__ void __launch_bounds__(256) edge_pass1(
    const float* __restrict__ x, const int* __restrict__ src, const int* __restrict__ dst,
    const float* __restrict__ ea, const float* __restrict__ W_edge, const float* __restrict__ tptr)
{
    __shared__ float wsh[DIM];
    int tid = threadIdx.x;
    if (tid < DIM) wsh[tid] = W_edge[tid];
    __syncthreads();
    const float t = tptr[0];
    int lane = tid & 31;
    int e = blockIdx.x * 8 + (tid >> 5);
    if (e >= N_EDGES) return;

    int s = src[e], d = dst[e];
    float a = ea[e];
    const float2* xp = (const float2*)(x + (size_t)s * DIM);
    float* base = g_agg + (size_t)d * (2 * DIM);

#pragma unroll
    for (int it = 0; it < 2; it++) {
        int c = it * 64 + lane * 2;
        float2 xv = xp[c >> 1];
        float m0 = fmaxf(xv.x + a * wsh[c],     0.f) + 1e-7f;
        float m1 = fmaxf(xv.y + a * wsh[c + 1], 0.f) + 1e-7f;
        float ex0 = __expf(m0 * t);
        float ex1 = __expf(m1 * t);
        float n0 = m0 * ex0, n1 = m1 * ex1;
        asm volatile("red.global.add.v4.f32 [%0], {%1,%2,%3,%4};"
                     :: "l"(base + c * 2), "f"(ex0), "f"(n0), "f"(ex1), "f"(n1)
                     : "memory");
    }
}

// ---------------- kernel 2: h = aggr + x ; h1 = h @ W1.T ; BN partial sums ----------------
// shared: Wsh[128][260] (W1 transposed, padded), hsh[64][128]
#define SMEM1 ((128 * 260 + 64 * 128) * 4)
__global__ void __launch_bounds__(256) gemm1(const float* __restrict__ x, const float* __restrict__ W1)
{
    extern __shared__ float sh[];
    float* Wsh = sh;                // [k<128][j<256] stride 260
    float* hsh = sh + 128 * 260;    // [r<64][k<128]
    int tid = threadIdx.x;
    int row0 = blockIdx.x * 64;

    for (int i = tid; i < 256 * 128; i += 256) {        // W1 is [256][128] (j,k) row-major
        int j = i >> 7, k = i & 127;
        Wsh[k * 260 + j] = W1[i];
    }
    for (int i = tid; i < 64 * 128; i += 256) {
        int r = i >> 7, k = i & 127;
        int row = row0 + r;
        float h = 0.f;
        if (row < N_NODES) {
            float2 ag = *(const float2*)(g_agg + ((size_t)row * DIM + k) * 2);
            h = ag.y / (ag.x + 1e-16f) + x[(size_t)row * DIM + k];
        }
        hsh[i] = h;
    }
    __syncthreads();

    int tc = tid & 31, tr = tid >> 5;
    int j0 = tc * 8, r0 = tr * 8;
    float acc[8][8];
#pragma unroll
    for (int i = 0; i < 8; i++)
#pragma unroll
        for (int j = 0; j < 8; j++) acc[i][j] = 0.f;

    for (int k = 0; k < 128; k += 4) {
        float4 hv4[8];
#pragma unroll
        for (int i = 0; i < 8; i++) hv4[i] = *(const float4*)&hsh[(r0 + i) * 128 + k];
#pragma unroll
        for (int kk = 0; kk < 4; kk++) {
            float4 wa = *(const float4*)&Wsh[(k + kk) * 260 + j0];
            float4 wb = *(const float4*)&Wsh[(k + kk) * 260 + j0 + 4];
            float w[8] = {wa.x, wa.y, wa.z, wa.w, wb.x, wb.y, wb.z, wb.w};
#pragma unroll
            for (int i = 0; i < 8; i++) {
                float hv = (&hv4[i].x)[kk];
#pragma unroll
                for (int j = 0; j < 8; j++) acc[i][j] = fmaf(hv, w[j], acc[i][j]);
            }
        }
    }

    float cs[8], cq[8];
#pragma unroll
    for (int j = 0; j < 8; j++) { cs[j] = 0.f; cq[j] = 0.f; }
#pragma unroll
    for (int i = 0; i < 8; i++) {
        int row = row0 + r0 + i;
        if (row < N_NODES) {
            *(float4*)(g_h1 + (size_t)row * 256 + j0)     = make_float4(acc[i][0], acc[i][1], acc[i][2], acc[i][3]);
            *(float4*)(g_h1 + (size_t)row * 256 + j0 + 4) = make_float4(acc[i][4], acc[i][5], acc[i][6], acc[i][7]);
#pragma unroll
            for (int j = 0; j < 8; j++) { cs[j] += acc[i][j]; cq[j] += acc[i][j] * acc[i][j]; }
        }
    }
#pragma unroll
    for (int j = 0; j < 8; j++) {
        atomicAdd(&g_bnsum[j0 + j],       cs[j]);
        atomicAdd(&g_bnsum[256 + j0 + j], cq[j]);
    }
}

// ---------------- kernel 2b: finalize BN stats ----------------
__global__ void bn_stat(const float* __restrict__ bng, const float* __restrict__ bnb)
{
    int j = threadIdx.x;   // 256 threads
    float s = g_bnsum[j], s2 = g_bnsum[256 + j];
    float mu = s * (1.0f / N_NODES);
    float var = s2 * (1.0f / N_NODES) - mu * mu;
    float rstd = rsqrtf(var + 1e-5f);
    float sc = rstd * bng[j];
    g_bnstat[j] = sc;
    g_bnstat[256 + j] = bnb[j] - mu * sc;
}

__device__ __forceinline__ float elu1(float v) { return v > 0.f ? v : expm1f(v); }

// ---------------- kernel 3: relu(bn(h1)) @ W2.T -> LN -> ELU -> out_x ----------------
// shared: Wsh[256][132], hsh[64][256]
#define SMEM2 ((256 * 132 + 64 * 256) * 4)
__global__ void __launch_bounds__(256) gemm2(
    const float* __restrict__ W2, const float* __restrict__ lng, const float* __restrict__ lnb,
    float* __restrict__ out_x)
{
    extern __shared__ float sh[];
    float* Wsh = sh;               // [k<256][j<128] stride 132
    float* hsh = sh + 256 * 132;   // [r<64][k<256]
    int tid = threadIdx.x;
    int row0 = blockIdx.x * 64;

    for (int i = tid; i < 128 * 256; i += 256) {   // W2 is [128][256] (j,k) row-major
        int j = i >> 8, k = i & 255;
        Wsh[k * 132 + j] = W2[i];
    }
    for (int i = tid; i < 64 * 256; i += 256) {
        int r = i >> 8, k = i & 255;
        int row = row0 + r;
        float v = 0.f;
        if (row < N_NODES) {
            float h = g_h1[(size_t)row * 256 + k];
            v = fmaxf(fmaf(h, g_bnstat[k], g_bnstat[256 + k]), 0.f);
        }
        hsh[i] = v;
    }
    __syncthreads();

    int tc = tid & 31, tr = tid >> 5;
    int j0 = tc * 4, r0 = tr * 8;
    float acc[8][4];
#pragma unroll
    for (int i = 0; i < 8; i++)
#pragma unroll
        for (int j = 0; j < 4; j++) acc[i][j] = 0.f;

    for (int k = 0; k < 256; k += 4) {
        float4 hv4[8];
#pragma unroll
        for (int i = 0; i < 8; i++) hv4[i] = *(const float4*)&hsh[(r0 + i) * 256 + k];
#pragma unroll
        for (int kk = 0; kk < 4; kk++) {
            float4 w = *(const float4*)&Wsh[(k + kk) * 132 + j0];
#pragma unroll
            for (int i = 0; i < 8; i++) {
                float hv = (&hv4[i].x)[kk];
                acc[i][0] = fmaf(hv, w.x, acc[i][0]);
                acc[i][1] = fmaf(hv, w.y, acc[i][1]);
                acc[i][2] = fmaf(hv, w.z, acc[i][2]);
                acc[i][3] = fmaf(hv, w.w, acc[i][3]);
            }
        }
    }

    float4 gv = *(const float4*)(lng + j0);
    float4 bv = *(const float4*)(lnb + j0);
#pragma unroll
    for (int i = 0; i < 8; i++) {
        int row = row0 + r0 + i;
        float s = acc[i][0] + acc[i][1] + acc[i][2] + acc[i][3];
        float q = acc[i][0] * acc[i][0] + acc[i][1] * acc[i][1] + acc[i][2] * acc[i][2] + acc[i][3] * acc[i][3];
#pragma unroll
        for (int o = 16; o > 0; o >>= 1) {
            s += __shfl_xor_sync(0xffffffffu, s, o);
            q += __shfl_xor_sync(0xffffffffu, q, o);
        }
        float mu = s * (1.f / 128.f);
        float var = q * (1.f / 128.f) - mu * mu;
        float rstd = rsqrtf(var + 1e-5f);
        if (row < N_NODES) {
            float4 o;
            o.x = elu1((acc[i][0] - mu) * rstd * gv.x + bv.x);
            o.y = elu1((acc[i][1] - mu) * rstd * gv.y + bv.y);
            o.z = elu1((acc[i][2] - mu) * rstd * gv.z + bv.z);
            o.w = elu1((acc[i][3] - mu) * rstd * gv.w + bv.w);
            *(float4*)(out_x + (size_t)row * DIM + j0) = o;
        }
    }
}

// ---------------- kernel 4: PQ = out_x @ [WeL | WeR].T ----------------
#define SMEM3 ((128 * 260 + 64 * 128) * 4)
__global__ void __launch_bounds__(256) gemm3(const float* __restrict__ out_x, const float* __restrict__ We)
{
    extern __shared__ float sh[];
    float* Wsh = sh;                // [k<128][jj<256] stride 260
    float* hsh = sh + 128 * 260;    // [r<64][k<128]
    int tid = threadIdx.x;
    int row0 = blockIdx.x * 64;

    // We is [128][256] (j, kcat) row-major. jj<128 -> We[jj][k]; jj>=128 -> We[jj-128][128+k]
    for (int i = tid; i < 256 * 128; i += 256) {
        int jj = i >> 7, k = i & 127;
        float w = (jj < 128) ? We[jj * 256 + k] : We[(jj - 128) * 256 + 128 + k];
        Wsh[k * 260 + jj] = w;
    }
    for (int i = tid; i < 64 * 128; i += 256) {
        int r = i >> 7, k = i & 127;
        int row = row0 + r;
        hsh[i] = (row < N_NODES) ? out_x[(size_t)row * DIM + k] : 0.f;
    }
    __syncthreads();

    int tc = tid & 31, tr = tid >> 5;
    int j0 = tc * 8, r0 = tr * 8;
    float acc[8][8];
#pragma unroll
    for (int i = 0; i < 8; i++)
#pragma unroll
        for (int j = 0; j < 8; j++) acc[i][j] = 0.f;

    for (int k = 0; k < 128; k += 4) {
        float4 hv4[8];
#pragma unroll
        for (int i = 0; i < 8; i++) hv4[i] = *(const float4*)&hsh[(r0 + i) * 128 + k];
#pragma unroll
        for (int kk = 0; kk < 4; kk++) {
            float4 wa = *(const float4*)&Wsh[(k + kk) * 260 + j0];
            float4 wb = *(const float4*)&Wsh[(k + kk) * 260 + j0 + 4];
            float w[8] = {wa.x, wa.y, wa.z, wa.w, wb.x, wb.y, wb.z, wb.w};
#pragma unroll
            for (int i = 0; i < 8; i++) {
                float hv = (&hv4[i].x)[kk];
#pragma unroll
                for (int j = 0; j < 8; j++) acc[i][j] = fmaf(hv, w[j], acc[i][j]);
            }
        }
    }
#pragma unroll
    for (int i = 0; i < 8; i++) {
        int row = row0 + r0 + i;
        if (row < N_NODES) {
            *(float4*)(g_PQ + (size_t)row * 256 + j0)     = make_float4(acc[i][0], acc[i][1], acc[i][2], acc[i][3]);
            *(float4*)(g_PQ + (size_t)row * 256 + j0 + 4) = make_float4(acc[i][4], acc[i][5], acc[i][6], acc[i][7]);
        }
    }
}

// ---------------- kernel 5: per-edge P[src]+Q[dst]+be -> GELU -> LN -> out_e ----------------
__global__ void __launch_bounds__(256) edge_out(
    const int* __restrict__ src, const int* __restrict__ dst,
    const float* __restrict__ be, const float* __restrict__ lng, const float* __restrict__ lnb,
    float* __restrict__ out_e)
{
    int tid = threadIdx.x;
    int lane = tid & 31;
    int j0 = lane * 4;
    float4 bev = *(const float4*)(be + j0);
    float4 gv  = *(const float4*)(lng + j0);
    float4 bv  = *(const float4*)(lnb + j0);

    int e = blockIdx.x * 8 + (tid >> 5);
    if (e >= N_EDGES) return;
    int s = src[e], d = dst[e];

    float4 p = *(const float4*)(g_PQ + (size_t)s * 256 + j0);
    float4 q = *(const float4*)(g_PQ + (size_t)d * 256 + 128 + j0);
    float g0, g1, g2, g3;
    {
        float v0 = p.x + q.x + bev.x;
        float v1 = p.y + q.y + bev.y;
        float v2 = p.z + q.z + bev.z;
        float v3 = p.w + q.w + bev.w;
        g0 = 0.5f * v0 * (1.f + erff(v0 * 0.70710678118654752f));
        g1 = 0.5f * v1 * (1.f + erff(v1 * 0.70710678118654752f));
        g2 = 0.5f * v2 * (1.f + erff(v2 * 0.70710678118654752f));
        g3 = 0.5f * v3 * (1.f + erff(v3 * 0.70710678118654752f));
    }
    float s1 = g0 + g1 + g2 + g3;
    float s2 = g0 * g0 + g1 * g1 + g2 * g2 + g3 * g3;
#pragma unroll
    for (int o = 16; o > 0; o >>= 1) {
        s1 += __shfl_xor_sync(0xffffffffu, s1, o);
        s2 += __shfl_xor_sync(0xffffffffu, s2, o);
    }
    float mu = s1 * (1.f / 128.f);
    float var = s2 * (1.f / 128.f) - mu * mu;
    float rstd = rsqrtf(var + 1e-5f);
    float4 o;
    o.x = (g0 - mu) * rstd * gv.x + bv.x;
    o.y = (g1 - mu) * rstd * gv.y + bv.y;
    o.z = (g2 - mu) * rstd * gv.z + bv.z;
    o.w = (g3 - mu) * rstd * gv.w + bv.w;
    *(float4*)(out_e + (size_t)e * DIM + j0) = o;
}

// ---------------- launch ----------------
extern "C" void kernel_launch(void* const* d_in, const int* in_sizes, int n_in,
                              void* d_out, int out_size)
{
    const float* x      = (const float*)d_in[0];
    const int*   ei     = (const int*)  d_in[1];
    const float* ea     = (const float*)d_in[2];
    const float* W_edge = (const float*)d_in[3];
    const float* tptr   = (const float*)d_in[4];
    const float* W1     = (const float*)d_in[5];
    const float* bng    = (const float*)d_in[6];
    const float* bnb    = (const float*)d_in[7];
    const float* W2     = (const float*)d_in[8];
    const float* lng    = (const float*)d_in[9];
    const float* lnb    = (const float*)d_in[10];
    const float* We     = (const float*)d_in[11];
    const float* be     = (const float*)d_in[12];
    const float* lneg   = (const float*)d_in[13];
    const float* lneb   = (const float*)d_in[14];

    const int* src = ei;
    const int* dst = ei + N_EDGES;

    float* out_x = (float*)d_out;
    float* out_e = out_x + (size_t)N_NODES * DIM;

    void *aggp, *bnp;
    cudaGetSymbolAddress(&aggp, g_agg);
    cudaGetSymbolAddress(&bnp, g_bnsum);
    cudaMemsetAsync(aggp, 0, sizeof(float) * (size_t)N_NODES * DIM * 2, 0);
    cudaMemsetAsync(bnp, 0, sizeof(float) * 512, 0);

    cudaFuncSetAttribute(gemm1, cudaFuncAttributeMaxDynamicSharedMemorySize, SMEM1);
    cudaFuncSetAttribute(gemm2, cudaFuncAttributeMaxDynamicSharedMemorySize, SMEM2);
    cudaFuncSetAttribute(gemm3, cudaFuncAttributeMaxDynamicSharedMemorySize, SMEM3);

    int eblocks = (N_EDGES + 7) / 8;
    int nblocks = (N_NODES + 63) / 64;

    edge_pass1<<<eblocks, 256>>>(x, src, dst, ea, W_edge, tptr);
    gemm1<<<nblocks, 256, SMEM1>>>(x, W1);
    bn_stat<<<1, 256>>>(bng, bnb);
    gemm2<<<nblocks, 256, SMEM2>>>(W2, lng, lnb, out_x);
    gemm3<<<nblocks, 256, SMEM3>>>(out_x, We);
    edge_out<<<eblocks, 256>>>(src, dst, be, lneg, lneb, out_e);
}

// round 2
// speedup vs baseline: 1.4598x; 1.4598x over previous
#include <cuda_runtime.h>
#include <math.h>
#include <stdint.h>

#define N_NODES 50000
#define N_EDGES 800000
#define DIM 128

typedef unsigned long long ull;

// ---------------- scratch (static device allocations) ----------------
__device__ float g_agg[(size_t)N_NODES * DIM * 2];   // interleaved (sum_exp, sum_msg_exp)
__device__ float g_h1[(size_t)N_NODES * 256];        // h @ W1.T
__device__ float g_PQ[(size_t)N_NODES * 256];        // [P | Q] per node
__device__ float g_bnsum[512];                       // col sums / sumsq
__device__ float g_bnstat[512];                      // fused scale / bias

// ---------------- f32x2 helpers ----------------
__device__ __forceinline__ void fma2(ull& d, ull a, ull b) {
    asm("fma.rn.f32x2 %0, %1, %2, %0;" : "+l"(d) : "l"(a), "l"(b));
}
__device__ __forceinline__ float2 unpack2(ull v) {
    float2 f;
    f.x = __uint_as_float((unsigned)(v & 0xffffffffu));
    f.y = __uint_as_float((unsigned)(v >> 32));
    return f;
}
union W4U { float4 f; ull u[2]; };

// ---------------- kernel 1: edge message + scatter softmax accumulation ----------------
__global__ void __launch_bounds__(256) edge_pass1(
    const float* __restrict__ x, const int* __restrict__ src, const int* __restrict__ dst,
    const float* __restrict__ ea, const float* __restrict__ W_edge, const float* __restrict__ tptr)
{
    __shared__ float wsh[DIM];
    int tid = threadIdx.x;
    if (tid < DIM) wsh[tid] = W_edge[tid];
    __syncthreads();
    const float t = tptr[0];
    int lane = tid & 31;
    int e = blockIdx.x * 8 + (tid >> 5);
    if (e >= N_EDGES) return;

    int s = src[e], d = dst[e];
    float a = ea[e];
    const float2* xp = (const float2*)(x + (size_t)s * DIM);
    float* base = g_agg + (size_t)d * (2 * DIM);

#pragma unroll
    for (int it = 0; it < 2; it++) {
        int c = it * 64 + lane * 2;
        float2 xv = xp[c >> 1];
        float m0 = fmaxf(xv.x + a * wsh[c],     0.f) + 1e-7f;
        float m1 = fmaxf(xv.y + a * wsh[c + 1], 0.f) + 1e-7f;
        float ex0 = __expf(m0 * t);
        float ex1 = __expf(m1 * t);
        float n0 = m0 * ex0, n1 = m1 * ex1;
        asm volatile("red.global.add.v4.f32 [%0], {%1,%2,%3,%4};"
                     :: "l"(base + c * 2), "f"(ex0), "f"(n0), "f"(ex1), "f"(n1)
                     : "memory");
    }
}

// ---------------- kernel 2: h = aggr + x ; h1 = h @ W1.T ; BN partial sums ----------------
// tile: 64 rows x 256 cols, K=128. 512 threads, thread = (rg<8, jl<64): 8 rows x 4 cols.
// smem: Wsh[128][260] + hsh2[64][128] duplicated float2
#define G1SMEM ((128 * 260 + 64 * 128 * 2) * 4)
__global__ void __launch_bounds__(512) gemm1(const float* __restrict__ x, const float* __restrict__ W1)
{
    extern __shared__ float sh[];
    float* Wsh  = sh;               // [k<128][j<256] stride 260
    float* hsh2 = sh + 128 * 260;   // [r<64][k<128] x2 (dup)
    int tid = threadIdx.x;
    int row0 = blockIdx.x * 64;

    for (int i = tid; i < 256 * 128; i += 512) {   // W1 [256j][128k] row-major
        int j = i >> 7, k = i & 127;
        Wsh[k * 260 + j] = W1[i];
    }
    for (int i = tid; i < 64 * 128; i += 512) {
        int r = i >> 7, k = i & 127;
        int row = row0 + r;
        float h = 0.f;
        if (row < N_NODES) {
            float2 ag = *(const float2*)(g_agg + ((size_t)row * DIM + k) * 2);
            h = ag.y / (ag.x + 1e-16f) + x[(size_t)row * DIM + k];
        }
        *(float2*)&hsh2[(size_t)i * 2] = make_float2(h, h);
    }
    __syncthreads();

    int jl = tid & 63, rg = tid >> 6;
    int j0 = jl * 4, r0 = rg * 8;
    ull acc[8][2];
#pragma unroll
    for (int i = 0; i < 8; i++) { acc[i][0] = 0ull; acc[i][1] = 0ull; }

#pragma unroll 4
    for (int k = 0; k < 128; k++) {
        W4U w; w.f = *(const float4*)&Wsh[k * 260 + j0];
        ull a_[8];
#pragma unroll
        for (int i = 0; i < 8; i++)
            a_[i] = *(const ull*)&hsh2[((r0 + i) * 128 + k) * 2];
#pragma unroll
        for (int i = 0; i < 8; i++) {
            fma2(acc[i][0], a_[i], w.u[0]);
            fma2(acc[i][1], a_[i], w.u[1]);
        }
    }

    // store + per-thread column partial sums
    float cs[4], cq[4];
#pragma unroll
    for (int j = 0; j < 4; j++) { cs[j] = 0.f; cq[j] = 0.f; }
#pragma unroll
    for (int i = 0; i < 8; i++) {
        int row = row0 + r0 + i;
        float2 p0 = unpack2(acc[i][0]);
        float2 p1 = unpack2(acc[i][1]);
        if (row < N_NODES) {
            *(float4*)(g_h1 + (size_t)row * 256 + j0) = make_float4(p0.x, p0.y, p1.x, p1.y);
            cs[0] += p0.x; cq[0] += p0.x * p0.x;
            cs[1] += p0.y; cq[1] += p0.y * p0.y;
            cs[2] += p1.x; cq[2] += p1.x * p1.x;
            cs[3] += p1.y; cq[3] += p1.y * p1.y;
        }
    }
    // block-level reduction over rg groups via smem (reuse hsh2)
    __syncthreads();
    float* red = hsh2;   // 512*8 floats = 16KB
#pragma unroll
    for (int q = 0; q < 4; q++) { red[tid * 8 + q] = cs[q]; red[tid * 8 + 4 + q] = cq[q]; }
    __syncthreads();
    {
        int jj = tid >> 3, q = tid & 7;   // tid<512: jj<64 col-group, q<8
        float s = 0.f;
#pragma unroll
        for (int rgk = 0; rgk < 8; rgk++) s += red[((rgk << 6) + jj) * 8 + q];
        int col = jj * 4 + (q & 3);
        atomicAdd(&g_bnsum[col + ((q >= 4) ? 256 : 0)], s);
    }
}

// ---------------- kernel 2b: finalize BN stats ----------------
__global__ void bn_stat(const float* __restrict__ bng, const float* __restrict__ bnb)
{
    int j = threadIdx.x;   // 256 threads
    float s = g_bnsum[j], s2 = g_bnsum[256 + j];
    float mu = s * (1.0f / N_NODES);
    float var = s2 * (1.0f / N_NODES) - mu * mu;
    float rstd = rsqrtf(var + 1e-5f);
    float sc = rstd * bng[j];
    g_bnstat[j] = sc;
    g_bnstat[256 + j] = bnb[j] - mu * sc;
}

__device__ __forceinline__ float elu1(float v) { return v > 0.f ? v : expm1f(v); }

// ---------------- kernel 3: relu(bn(h1)) @ W2.T -> LN -> ELU -> out_x ----------------
// tile: 64 rows x 128 cols, K=256 staged in two 128-k halves.
// 512 threads, thread = (rg<16, jl<32): 4 rows x 4 cols.
// smem: Wsh[256][132] + hsh2[64][128] dup float2
#define G2SMEM ((256 * 132 + 64 * 128 * 2) * 4)
__global__ void __launch_bounds__(512) gemm2(
    const float* __restrict__ W2, const float* __restrict__ lng, const float* __restrict__ lnb,
    float* __restrict__ out_x)
{
    extern __shared__ float sh[];
    float* Wsh  = sh;               // [k<256][j<128] stride 132
    float* hsh2 = sh + 256 * 132;   // [r<64][k<128] x2 dup (per stage)
    int tid = threadIdx.x;
    int row0 = blockIdx.x * 64;

    for (int i = tid; i < 128 * 256; i += 512) {   // W2 [128j][256k] row-major
        int j = i >> 8, k = i & 255;
        Wsh[k * 132 + j] = W2[i];
    }

    int jl = tid & 31, rg = tid >> 5;
    int j0 = jl * 4, r0 = rg * 4;
    ull acc[4][2];
#pragma unroll
    for (int i = 0; i < 4; i++) { acc[i][0] = 0ull; acc[i][1] = 0ull; }

#pragma unroll
    for (int s = 0; s < 2; s++) {
        __syncthreads();
        for (int i = tid; i < 64 * 128; i += 512) {
            int r = i >> 7, k = i & 127;
            int row = row0 + r;
            float v = 0.f;
            if (row < N_NODES) {
                int kc = s * 128 + k;
                float h = g_h1[(size_t)row * 256 + kc];
                v = fmaxf(fmaf(h, g_bnstat[kc], g_bnstat[256 + kc]), 0.f);
            }
            *(float2*)&hsh2[(size_t)i * 2] = make_float2(v, v);
        }
        __syncthreads();

#pragma unroll 4
        for (int k = 0; k < 128; k++) {
            W4U w; w.f = *(const float4*)&Wsh[(s * 128 + k) * 132 + j0];
            ull a_[4];
#pragma unroll
            for (int i = 0; i < 4; i++)
                a_[i] = *(const ull*)&hsh2[((r0 + i) * 128 + k) * 2];
#pragma unroll
            for (int i = 0; i < 4; i++) {
                fma2(acc[i][0], a_[i], w.u[0]);
                fma2(acc[i][1], a_[i], w.u[1]);
            }
        }
    }

    float4 gv = *(const float4*)(lng + j0);
    float4 bv = *(const float4*)(lnb + j0);
#pragma unroll
    for (int i = 0; i < 4; i++) {
        int row = row0 + r0 + i;
        float2 p0 = unpack2(acc[i][0]);
        float2 p1 = unpack2(acc[i][1]);
        float s1 = p0.x + p0.y + p1.x + p1.y;
        float s2 = p0.x * p0.x + p0.y * p0.y + p1.x * p1.x + p1.y * p1.y;
#pragma unroll
        for (int o = 16; o > 0; o >>= 1) {
            s1 += __shfl_xor_sync(0xffffffffu, s1, o);
            s2 += __shfl_xor_sync(0xffffffffu, s2, o);
        }
        float mu = s1 * (1.f / 128.f);
        float var = s2 * (1.f / 128.f) - mu * mu;
        float rstd = rsqrtf(var + 1e-5f);
        if (row < N_NODES) {
            float4 o;
            o.x = elu1((p0.x - mu) * rstd * gv.x + bv.x);
            o.y = elu1((p0.y - mu) * rstd * gv.y + bv.y);
            o.z = elu1((p1.x - mu) * rstd * gv.z + bv.z);
            o.w = elu1((p1.y - mu) * rstd * gv.w + bv.w);
            *(float4*)(out_x + (size_t)row * DIM + j0) = o;
        }
    }
}

// ---------------- kernel 4: PQ = out_x @ [WeL | WeR].T ----------------
// same geometry as gemm1 (64 x 256, K=128)
#define G3SMEM G1SMEM
__global__ void __launch_bounds__(512) gemm3(const float* __restrict__ out_x, const float* __restrict__ We)
{
    extern __shared__ float sh[];
    float* Wsh  = sh;               // [k<128][jj<256] stride 260
    float* hsh2 = sh + 128 * 260;   // [r<64][k<128] x2 dup
    int tid = threadIdx.x;
    int row0 = blockIdx.x * 64;

    // We [128j][256kcat] row-major. jj<128 -> We[jj][k]; jj>=128 -> We[jj-128][128+k]
    for (int i = tid; i < 256 * 128; i += 512) {
        int jj = i >> 7, k = i & 127;
        float w = (jj < 128) ? We[jj * 256 + k] : We[(jj - 128) * 256 + 128 + k];
        Wsh[k * 260 + jj] = w;
    }
    for (int i = tid; i < 64 * 128; i += 512) {
        int r = i >> 7, k = i & 127;
        int row = row0 + r;
        float h = (row < N_NODES) ? out_x[(size_t)row * DIM + k] : 0.f;
        *(float2*)&hsh2[(size_t)i * 2] = make_float2(h, h);
    }
    __syncthreads();

    int jl = tid & 63, rg = tid >> 6;
    int j0 = jl * 4, r0 = rg * 8;
    ull acc[8][2];
#pragma unroll
    for (int i = 0; i < 8; i++) { acc[i][0] = 0ull; acc[i][1] = 0ull; }

#pragma unroll 4
    for (int k = 0; k < 128; k++) {
        W4U w; w.f = *(const float4*)&Wsh[k * 260 + j0];
        ull a_[8];
#pragma unroll
        for (int i = 0; i < 8; i++)
            a_[i] = *(const ull*)&hsh2[((r0 + i) * 128 + k) * 2];
#pragma unroll
        for (int i = 0; i < 8; i++) {
            fma2(acc[i][0], a_[i], w.u[0]);
            fma2(acc[i][1], a_[i], w.u[1]);
        }
    }
#pragma unroll
    for (int i = 0; i < 8; i++) {
        int row = row0 + r0 + i;
        if (row < N_NODES) {
            float2 p0 = unpack2(acc[i][0]);
            float2 p1 = unpack2(acc[i][1]);
            *(float4*)(g_PQ + (size_t)row * 256 + j0) = make_float4(p0.x, p0.y, p1.x, p1.y);
        }
    }
}

// ---------------- kernel 5: per-edge P[src]+Q[dst]+be -> GELU -> LN -> out_e ----------------
__global__ void __launch_bounds__(256) edge_out(
    const int* __restrict__ src, const int* __restrict__ dst,
    const float* __restrict__ be, const float* __restrict__ lng, const float* __restrict__ lnb,
    float* __restrict__ out_e)
{
    int tid = threadIdx.x;
    int lane = tid & 31;
    int j0 = lane * 4;
    float4 bev = *(const float4*)(be + j0);
    float4 gv  = *(const float4*)(lng + j0);
    float4 bv  = *(const float4*)(lnb + j0);

    int e = blockIdx.x * 8 + (tid >> 5);
    if (e >= N_EDGES) return;
    int s = src[e], d = dst[e];

    float4 p = *(const float4*)(g_PQ + (size_t)s * 256 + j0);
    float4 q = *(const float4*)(g_PQ + (size_t)d * 256 + 128 + j0);
    float g0, g1, g2, g3;
    {
        float v0 = p.x + q.x + bev.x;
        float v1 = p.y + q.y + bev.y;
        float v2 = p.z + q.z + bev.z;
        float v3 = p.w + q.w + bev.w;
        g0 = 0.5f * v0 * (1.f + erff(v0 * 0.70710678118654752f));
        g1 = 0.5f * v1 * (1.f + erff(v1 * 0.70710678118654752f));
        g2 = 0.5f * v2 * (1.f + erff(v2 * 0.70710678118654752f));
        g3 = 0.5f * v3 * (1.f + erff(v3 * 0.70710678118654752f));
    }
    float s1 = g0 + g1 + g2 + g3;
    float s2 = g0 * g0 + g1 * g1 + g2 * g2 + g3 * g3;
#pragma unroll
    for (int o = 16; o > 0; o >>= 1) {
        s1 += __shfl_xor_sync(0xffffffffu, s1, o);
        s2 += __shfl_xor_sync(0xffffffffu, s2, o);
    }
    float mu = s1 * (1.f / 128.f);
    float var = s2 * (1.f / 128.f) - mu * mu;
    float rstd = rsqrtf(var + 1e-5f);
    float4 o;
    o.x = (g0 - mu) * rstd * gv.x + bv.x;
    o.y = (g1 - mu) * rstd * gv.y + bv.y;
    o.z = (g2 - mu) * rstd * gv.z + bv.z;
    o.w = (g3 - mu) * rstd * gv.w + bv.w;
    *(float4*)(out_e + (size_t)e * DIM + j0) = o;
}

// ---------------- launch ----------------
extern "C" void kernel_launch(void* const* d_in, const int* in_sizes, int n_in,
                              void* d_out, int out_size)
{
    const float* x      = (const float*)d_in[0];
    const int*   ei     = (const int*)  d_in[1];
    const float* ea     = (const float*)d_in[2];
    const float* W_edge = (const float*)d_in[3];
    const float* tptr   = (const float*)d_in[4];
    const float* W1     = (const float*)d_in[5];
    const float* bng    = (const float*)d_in[6];
    const float* bnb    = (const float*)d_in[7];
    const float* W2     = (const float*)d_in[8];
    const float* lng    = (const float*)d_in[9];
    const float* lnb    = (const float*)d_in[10];
    const float* We     = (const float*)d_in[11];
    const float* be     = (const float*)d_in[12];
    const float* lneg   = (const float*)d_in[13];
    const float* lneb   = (const float*)d_in[14];

    const int* src = ei;
    const int* dst = ei + N_EDGES;

    float* out_x = (float*)d_out;
    float* out_e = out_x + (size_t)N_NODES * DIM;

    void *aggp, *bnp;
    cudaGetSymbolAddress(&aggp, g_agg);
    cudaGetSymbolAddress(&bnp, g_bnsum);
    cudaMemsetAsync(aggp, 0, sizeof(float) * (size_t)N_NODES * DIM * 2, 0);
    cudaMemsetAsync(bnp, 0, sizeof(float) * 512, 0);

    cudaFuncSetAttribute(gemm1, cudaFuncAttributeMaxDynamicSharedMemorySize, G1SMEM);
    cudaFuncSetAttribute(gemm2, cudaFuncAttributeMaxDynamicSharedMemorySize, G2SMEM);
    cudaFuncSetAttribute(gemm3, cudaFuncAttributeMaxDynamicSharedMemorySize, G3SMEM);

    int eblocks = (N_EDGES + 7) / 8;
    int nblocks = (N_NODES + 63) / 64;

    edge_pass1<<<eblocks, 256>>>(x, src, dst, ea, W_edge, tptr);
    gemm1<<<nblocks, 512, G1SMEM>>>(x, W1);
    bn_stat<<<1, 256>>>(bng, bnb);
    gemm2<<<nblocks, 512, G2SMEM>>>(W2, lng, lnb, out_x);
    gemm3<<<nblocks, 512, G3SMEM>>>(out_x, We);
    edge_out<<<eblocks, 256>>>(src, dst, be, lneg, lneb, out_e);
}

// round 3
// speedup vs baseline: 1.6623x; 1.1387x over previous
#include <cuda_runtime.h>
#include <math.h>
#include <stdint.h>

#define N_NODES 50000
#define N_EDGES 800000
#define DIM 128

typedef unsigned long long ull;

// ---------------- scratch ----------------
__device__ float g_agg[(size_t)N_NODES * DIM * 2];   // interleaved (sum_exp, sum_msg_exp)
__device__ float g_h1[(size_t)N_NODES * 256];        // h @ W1.T
__device__ float g_PQ[(size_t)N_NODES * 256];        // [P | Q] per node
__device__ float g_bnsum[512];
__device__ float g_bnstat[512];
__device__ float g_W1T[128 * 256];                   // W1T[k][j]
__device__ float g_W2T[256 * 128];                   // W2T[k][j]
__device__ float g_WeT[256 * 128];                   // WeT0[kcat][j]

// ---------------- f32x2 helpers ----------------
__device__ __forceinline__ void fma2(ull& d, ull a, ull b) {
    asm("fma.rn.f32x2 %0, %1, %2, %0;" : "+l"(d) : "l"(a), "l"(b));
}
__device__ __forceinline__ ull pack_dup(float a) {
    ull r;
    asm("mov.b64 %0, {%1, %1};" : "=l"(r) : "f"(a));
    return r;
}
__device__ __forceinline__ float2 unpack2(ull v) {
    float2 f;
    f.x = __uint_as_float((unsigned)(v & 0xffffffffu));
    f.y = __uint_as_float((unsigned)(v >> 32));
    return f;
}
union W4U { float4 f; ull u[2]; };

// ---------------- weight transpose: in[J][K] -> out[K][J] ----------------
__global__ void __launch_bounds__(256) transp(const float* __restrict__ in, float* __restrict__ out,
                                              int J, int K)
{
    __shared__ float t[32][33];
    int bj = blockIdx.x * 32, bk = blockIdx.y * 32;
    int tx = threadIdx.x & 31, ty = threadIdx.x >> 5;
#pragma unroll
    for (int r = ty; r < 32; r += 8)
        t[r][tx] = in[(size_t)(bj + r) * K + bk + tx];
    __syncthreads();
#pragma unroll
    for (int r = ty; r < 32; r += 8)
        out[(size_t)(bk + r) * J + bj + tx] = t[tx][r];
}

// ---------------- kernel 1: edge message + scatter softmax accumulation ----------------
__global__ void __launch_bounds__(256) edge_pass1(
    const float* __restrict__ x, const int* __restrict__ src, const int* __restrict__ dst,
    const float* __restrict__ ea, const float* __restrict__ W_edge, const float* __restrict__ tptr)
{
    __shared__ float wsh[DIM];
    int tid = threadIdx.x;
    if (tid < DIM) wsh[tid] = W_edge[tid];
    __syncthreads();
    const float t = tptr[0];
    int lane = tid & 31;
    int e = blockIdx.x * 8 + (tid >> 5);
    if (e >= N_EDGES) return;

    int s = src[e], d = dst[e];
    float a = ea[e];
    const float2* xp = (const float2*)(x + (size_t)s * DIM);
    float* base = g_agg + (size_t)d * (2 * DIM);

#pragma unroll
    for (int it = 0; it < 2; it++) {
        int c = it * 64 + lane * 2;
        float2 xv = xp[c >> 1];
        float m0 = fmaxf(xv.x + a * wsh[c],     0.f) + 1e-7f;
        float m1 = fmaxf(xv.y + a * wsh[c + 1], 0.f) + 1e-7f;
        float ex0 = __expf(m0 * t);
        float ex1 = __expf(m1 * t);
        float n0 = m0 * ex0, n1 = m1 * ex1;
        asm volatile("red.global.add.v4.f32 [%0], {%1,%2,%3,%4};"
                     :: "l"(base + c * 2), "f"(ex0), "f"(n0), "f"(ex1), "f"(n1)
                     : "memory");
    }
}

// ============================================================================
// gemm1: h = aggr + x ; g_h1 = h @ W1.T (out 256 cols) ; BN partial sums
// tile 64 rows x 256 cols, K=128, 256 threads, 8x8 per thread
// ============================================================================
#define G1SMEM ((128 * 260 + 128 * 68) * 4)
__global__ void __launch_bounds__(256) gemm1(const float* __restrict__ x)
{
    extern __shared__ float sh[];
    float* Wsh  = sh;               // [k<128][j<256] stride 260
    float* hshT = sh + 128 * 260;   // [k<128][r<64]  stride 68
    int tid = threadIdx.x;
    int row0 = blockIdx.x * 64;

    for (int i = tid; i < 128 * 64; i += 256) {     // float4 copies, conflict-free
        int k = i >> 6, j4 = (i & 63) << 2;
        *(float4*)&Wsh[k * 260 + j4] = *(const float4*)&g_W1T[k * 256 + j4];
    }
    for (int i = tid; i < 64 * 64; i += 256) {
        int r = i >> 6, k2 = (i & 63) << 1;
        int row = row0 + r;
        float h0 = 0.f, h1 = 0.f;
        if (row < N_NODES) {
            float4 ag = *(const float4*)&g_agg[((size_t)row * 128 + k2) * 2];
            float2 xv = *(const float2*)&x[(size_t)row * 128 + k2];
            h0 = ag.y / (ag.x + 1e-16f) + xv.x;
            h1 = ag.w / (ag.z + 1e-16f) + xv.y;
        }
        hshT[k2 * 68 + r] = h0;
        hshT[(k2 + 1) * 68 + r] = h1;
    }
    __syncthreads();

    int tc = tid & 31, tr = tid >> 5;
    int j0 = tc * 8, r0 = tr * 8;
    ull acc[8][4];
#pragma unroll
    for (int i = 0; i < 8; i++)
#pragma unroll
        for (int jp = 0; jp < 4; jp++) acc[i][jp] = 0ull;

#pragma unroll 4
    for (int k = 0; k < 128; k++) {
        W4U wa, wb;
        wa.f = *(const float4*)&Wsh[k * 260 + j0];
        wb.f = *(const float4*)&Wsh[k * 260 + j0 + 4];
        float4 a0 = *(const float4*)&hshT[k * 68 + r0];
        float4 a1 = *(const float4*)&hshT[k * 68 + r0 + 4];
        float af[8] = {a0.x, a0.y, a0.z, a0.w, a1.x, a1.y, a1.z, a1.w};
#pragma unroll
        for (int i = 0; i < 8; i++) {
            ull A = pack_dup(af[i]);
            fma2(acc[i][0], A, wa.u[0]);
            fma2(acc[i][1], A, wa.u[1]);
            fma2(acc[i][2], A, wb.u[0]);
            fma2(acc[i][3], A, wb.u[1]);
        }
    }

    float cs[8], cq[8];
#pragma unroll
    for (int c = 0; c < 8; c++) { cs[c] = 0.f; cq[c] = 0.f; }
#pragma unroll
    for (int i = 0; i < 8; i++) {
        int row = row0 + r0 + i;
        if (row < N_NODES) {
            float2 p0 = unpack2(acc[i][0]);
            float2 p1 = unpack2(acc[i][1]);
            float2 p2 = unpack2(acc[i][2]);
            float2 p3 = unpack2(acc[i][3]);
            *(float4*)(g_h1 + (size_t)row * 256 + j0)     = make_float4(p0.x, p0.y, p1.x, p1.y);
            *(float4*)(g_h1 + (size_t)row * 256 + j0 + 4) = make_float4(p2.x, p2.y, p3.x, p3.y);
            float v[8] = {p0.x, p0.y, p1.x, p1.y, p2.x, p2.y, p3.x, p3.y};
#pragma unroll
            for (int c = 0; c < 8; c++) { cs[c] += v[c]; cq[c] += v[c] * v[c]; }
        }
    }
    __syncthreads();
    float* red = hshT;   // 256*16 = 4096 floats, fits
#pragma unroll
    for (int c = 0; c < 8; c++) { red[tid * 16 + c] = cs[c]; red[tid * 16 + 8 + c] = cq[c]; }
    __syncthreads();
    {
        int c = tid;                 // 256 threads -> 256 cols
        int tcq = c >> 3, jc = c & 7;
        float s = 0.f, q = 0.f;
#pragma unroll
        for (int trq = 0; trq < 8; trq++) {
            int idx = ((trq << 5) + tcq) * 16;
            s += red[idx + jc];
            q += red[idx + 8 + jc];
        }
        atomicAdd(&g_bnsum[c], s);
        atomicAdd(&g_bnsum[256 + c], q);
    }
}

// ---------------- bn stats finalize ----------------
__global__ void bn_stat(const float* __restrict__ bng, const float* __restrict__ bnb)
{
    int j = threadIdx.x;
    float s = g_bnsum[j], s2 = g_bnsum[256 + j];
    float mu = s * (1.0f / N_NODES);
    float var = s2 * (1.0f / N_NODES) - mu * mu;
    float rstd = rsqrtf(var + 1e-5f);
    float sc = rstd * bng[j];
    g_bnstat[j] = sc;
    g_bnstat[256 + j] = bnb[j] - mu * sc;
}

__device__ __forceinline__ float elu1(float v) { return v > 0.f ? v : expm1f(v); }

// ============================================================================
// gemm2: relu(bn(g_h1)) @ W2.T (out 128 cols, K=256 in 2 stages) -> LN -> ELU -> out_x
// tile 64 rows x 128 cols, 256 threads, 8x4 per thread
// ============================================================================
#define G2SMEM ((256 * 132 + 128 * 68) * 4)
__global__ void __launch_bounds__(256) gemm2(
    const float* __restrict__ lng, const float* __restrict__ lnb, float* __restrict__ out_x)
{
    extern __shared__ float sh[];
    float* Wsh  = sh;               // [k<256][j<128] stride 132
    float* hshT = sh + 256 * 132;   // [k<128][r<64]  stride 68
    int tid = threadIdx.x;
    int row0 = blockIdx.x * 64;

    for (int i = tid; i < 256 * 32; i += 256) {   // conflict-free float4
        int k = i >> 5, j4 = (i & 31) << 2;
        *(float4*)&Wsh[k * 132 + j4] = *(const float4*)&g_W2T[k * 128 + j4];
    }

    int tc = tid & 31, tr = tid >> 5;
    int j0 = tc * 4, r0 = tr * 8;
    ull acc[8][2];
#pragma unroll
    for (int i = 0; i < 8; i++) { acc[i][0] = 0ull; acc[i][1] = 0ull; }

#pragma unroll
    for (int s = 0; s < 2; s++) {
        __syncthreads();
        for (int i = tid; i < 64 * 64; i += 256) {
            int r = i >> 6, k2 = (i & 63) << 1;
            int row = row0 + r;
            float v0 = 0.f, v1 = 0.f;
            if (row < N_NODES) {
                int kc = s * 128 + k2;
                float2 hv = *(const float2*)&g_h1[(size_t)row * 256 + kc];
                v0 = fmaxf(fmaf(hv.x, g_bnstat[kc],     g_bnstat[256 + kc]),     0.f);
                v1 = fmaxf(fmaf(hv.y, g_bnstat[kc + 1], g_bnstat[256 + kc + 1]), 0.f);
            }
            hshT[k2 * 68 + r] = v0;
            hshT[(k2 + 1) * 68 + r] = v1;
        }
        __syncthreads();

#pragma unroll 4
        for (int k = 0; k < 128; k++) {
            W4U w;
            w.f = *(const float4*)&Wsh[(s * 128 + k) * 132 + j0];
            float4 a0 = *(const float4*)&hshT[k * 68 + r0];
            float4 a1 = *(const float4*)&hshT[k * 68 + r0 + 4];
            float af[8] = {a0.x, a0.y, a0.z, a0.w, a1.x, a1.y, a1.z, a1.w};
#pragma unroll
            for (int i = 0; i < 8; i++) {
                ull A = pack_dup(af[i]);
                fma2(acc[i][0], A, w.u[0]);
                fma2(acc[i][1], A, w.u[1]);
            }
        }
    }

    float4 gv = *(const float4*)(lng + j0);
    float4 bv = *(const float4*)(lnb + j0);
#pragma unroll
    for (int i = 0; i < 8; i++) {
        int row = row0 + r0 + i;
        float2 p0 = unpack2(acc[i][0]);
        float2 p1 = unpack2(acc[i][1]);
        float s1 = p0.x + p0.y + p1.x + p1.y;
        float s2 = p0.x * p0.x + p0.y * p0.y + p1.x * p1.x + p1.y * p1.y;
#pragma unroll
        for (int o = 16; o > 0; o >>= 1) {
            s1 += __shfl_xor_sync(0xffffffffu, s1, o);
            s2 += __shfl_xor_sync(0xffffffffu, s2, o);
        }
        float mu = s1 * (1.f / 128.f);
        float var = s2 * (1.f / 128.f) - mu * mu;
        float rstd = rsqrtf(var + 1e-5f);
        if (row < N_NODES) {
            float4 o;
            o.x = elu1((p0.x - mu) * rstd * gv.x + bv.x);
            o.y = elu1((p0.y - mu) * rstd * gv.y + bv.y);
            o.z = elu1((p1.x - mu) * rstd * gv.z + bv.z);
            o.w = elu1((p1.y - mu) * rstd * gv.w + bv.w);
            *(float4*)(out_x + (size_t)row * DIM + j0) = o;
        }
    }
}

// ============================================================================
// gemm3: g_PQ = out_x @ [WeL | WeR].T (out 256 cols, K=128)
// same geometry as gemm1
// ============================================================================
#define G3SMEM G1SMEM
__global__ void __launch_bounds__(256) gemm3(const float* __restrict__ out_x)
{
    extern __shared__ float sh[];
    float* Wsh  = sh;               // [k<128][jj<256] stride 260
    float* hshT = sh + 128 * 260;   // [k<128][r<64] stride 68
    int tid = threadIdx.x;
    int row0 = blockIdx.x * 64;

    // WeT0 is [kcat<256][j<128]; Wsh[k][jj] : jj<128 -> WeT0[k][jj], else WeT0[128+k][jj-128]
    for (int i = tid; i < 128 * 64; i += 256) {
        int k = i >> 6, j4 = (i & 63) << 2;
        const float* srcp = (j4 < 128) ? &g_WeT[k * 128 + j4]
                                       : &g_WeT[(128 + k) * 128 + (j4 - 128)];
        *(float4*)&Wsh[k * 260 + j4] = *(const float4*)srcp;
    }
    for (int i = tid; i < 64 * 64; i += 256) {
        int r = i >> 6, k2 = (i & 63) << 1;
        int row = row0 + r;
        float2 hv = make_float2(0.f, 0.f);
        if (row < N_NODES) hv = *(const float2*)&out_x[(size_t)row * DIM + k2];
        hshT[k2 * 68 + r] = hv.x;
        hshT[(k2 + 1) * 68 + r] = hv.y;
    }
    __syncthreads();

    int tc = tid & 31, tr = tid >> 5;
    int j0 = tc * 8, r0 = tr * 8;
    ull acc[8][4];
#pragma unroll
    for (int i = 0; i < 8; i++)
#pragma unroll
        for (int jp = 0; jp < 4; jp++) acc[i][jp] = 0ull;

#pragma unroll 4
    for (int k = 0; k < 128; k++) {
        W4U wa, wb;
        wa.f = *(const float4*)&Wsh[k * 260 + j0];
        wb.f = *(const float4*)&Wsh[k * 260 + j0 + 4];
        float4 a0 = *(const float4*)&hshT[k * 68 + r0];
        float4 a1 = *(const float4*)&hshT[k * 68 + r0 + 4];
        float af[8] = {a0.x, a0.y, a0.z, a0.w, a1.x, a1.y, a1.z, a1.w};
#pragma unroll
        for (int i = 0; i < 8; i++) {
            ull A = pack_dup(af[i]);
            fma2(acc[i][0], A, wa.u[0]);
            fma2(acc[i][1], A, wa.u[1]);
            fma2(acc[i][2], A, wb.u[0]);
            fma2(acc[i][3], A, wb.u[1]);
        }
    }
#pragma unroll
    for (int i = 0; i < 8; i++) {
        int row = row0 + r0 + i;
        if (row < N_NODES) {
            float2 p0 = unpack2(acc[i][0]);
            float2 p1 = unpack2(acc[i][1]);
            float2 p2 = unpack2(acc[i][2]);
            float2 p3 = unpack2(acc[i][3]);
            *(float4*)(g_PQ + (size_t)row * 256 + j0)     = make_float4(p0.x, p0.y, p1.x, p1.y);
            *(float4*)(g_PQ + (size_t)row * 256 + j0 + 4) = make_float4(p2.x, p2.y, p3.x, p3.y);
        }
    }
}

// ---------------- kernel 5: per-edge P[src]+Q[dst]+be -> GELU -> LN -> out_e ----------------
__global__ void __launch_bounds__(256) edge_out(
    const int* __restrict__ src, const int* __restrict__ dst,
    const float* __restrict__ be, const float* __restrict__ lng, const float* __restrict__ lnb,
    float* __restrict__ out_e)
{
    int tid = threadIdx.x;
    int lane = tid & 31;
    int j0 = lane * 4;
    float4 bev = *(const float4*)(be + j0);
    float4 gv  = *(const float4*)(lng + j0);
    float4 bv  = *(const float4*)(lnb + j0);

    int e = blockIdx.x * 8 + (tid >> 5);
    if (e >= N_EDGES) return;
    int s = src[e], d = dst[e];

    float4 p = *(const float4*)(g_PQ + (size_t)s * 256 + j0);
    float4 q = *(const float4*)(g_PQ + (size_t)d * 256 + 128 + j0);
    float g0, g1, g2, g3;
    {
        float v0 = p.x + q.x + bev.x;
        float v1 = p.y + q.y + bev.y;
        float v2 = p.z + q.z + bev.z;
        float v3 = p.w + q.w + bev.w;
        g0 = 0.5f * v0 * (1.f + erff(v0 * 0.70710678118654752f));
        g1 = 0.5f * v1 * (1.f + erff(v1 * 0.70710678118654752f));
        g2 = 0.5f * v2 * (1.f + erff(v2 * 0.70710678118654752f));
        g3 = 0.5f * v3 * (1.f + erff(v3 * 0.70710678118654752f));
    }
    float s1 = g0 + g1 + g2 + g3;
    float s2 = g0 * g0 + g1 * g1 + g2 * g2 + g3 * g3;
#pragma unroll
    for (int o = 16; o > 0; o >>= 1) {
        s1 += __shfl_xor_sync(0xffffffffu, s1, o);
        s2 += __shfl_xor_sync(0xffffffffu, s2, o);
    }
    float mu = s1 * (1.f / 128.f);
    float var = s2 * (1.f / 128.f) - mu * mu;
    float rstd = rsqrtf(var + 1e-5f);
    float4 o;
    o.x = (g0 - mu) * rstd * gv.x + bv.x;
    o.y = (g1 - mu) * rstd * gv.y + bv.y;
    o.z = (g2 - mu) * rstd * gv.z + bv.z;
    o.w = (g3 - mu) * rstd * gv.w + bv.w;
    *(float4*)(out_e + (size_t)e * DIM + j0) = o;
}

// ---------------- launch ----------------
extern "C" void kernel_launch(void* const* d_in, const int* in_sizes, int n_in,
                              void* d_out, int out_size)
{
    const float* x      = (const float*)d_in[0];
    const int*   ei     = (const int*)  d_in[1];
    const float* ea     = (const float*)d_in[2];
    const float* W_edge = (const float*)d_in[3];
    const float* tptr   = (const float*)d_in[4];
    const float* W1     = (const float*)d_in[5];
    const float* bng    = (const float*)d_in[6];
    const float* bnb    = (const float*)d_in[7];
    const float* W2     = (const float*)d_in[8];
    const float* lng    = (const float*)d_in[9];
    const float* lnb    = (const float*)d_in[10];
    const float* We     = (const float*)d_in[11];
    const float* be     = (const float*)d_in[12];
    const float* lneg   = (const float*)d_in[13];
    const float* lneb   = (const float*)d_in[14];

    const int* src = ei;
    const int* dst = ei + N_EDGES;

    float* out_x = (float*)d_out;
    float* out_e = out_x + (size_t)N_NODES * DIM;

    void *aggp, *bnp, *w1tp, *w2tp, *wetp;
    cudaGetSymbolAddress(&aggp, g_agg);
    cudaGetSymbolAddress(&bnp, g_bnsum);
    cudaGetSymbolAddress(&w1tp, g_W1T);
    cudaGetSymbolAddress(&w2tp, g_W2T);
    cudaGetSymbolAddress(&wetp, g_WeT);
    cudaMemsetAsync(aggp, 0, sizeof(float) * (size_t)N_NODES * DIM * 2, 0);
    cudaMemsetAsync(bnp, 0, sizeof(float) * 512, 0);

    cudaFuncSetAttribute(gemm1, cudaFuncAttributeMaxDynamicSharedMemorySize, G1SMEM);
    cudaFuncSetAttribute(gemm2, cudaFuncAttributeMaxDynamicSharedMemorySize, G2SMEM);
    cudaFuncSetAttribute(gemm3, cudaFuncAttributeMaxDynamicSharedMemorySize, G3SMEM);

    int eblocks = (N_EDGES + 7) / 8;
    int nblocks = (N_NODES + 63) / 64;

    transp<<<dim3(8, 4), 256>>>(W1, (float*)w1tp, 256, 128);   // W1[256][128] -> W1T[128][256]
    transp<<<dim3(4, 8), 256>>>(W2, (float*)w2tp, 128, 256);   // W2[128][256] -> W2T[256][128]
    transp<<<dim3(4, 8), 256>>>(We, (float*)wetp, 128, 256);   // We[128][256] -> WeT0[256][128]

    edge_pass1<<<eblocks, 256>>>(x, src, dst, ea, W_edge, tptr);
    gemm1<<<nblocks, 256, G1SMEM>>>(x);
    bn_stat<<<1, 256>>>(bng, bnb);
    gemm2<<<nblocks, 256, G2SMEM>>>(lng, lnb, out_x);
    gemm3<<<nblocks, 256, G3SMEM>>>(out_x);
    edge_out<<<eblocks, 256>>>(src, dst, be, lneg, lneb, out_e);
}

// round 4
// speedup vs baseline: 1.8338x; 1.1032x over previous
#include <cuda_runtime.h>
#include <math.h>
#include <stdint.h>

#define N_NODES 50000
#define N_EDGES 800000
#define DIM 128

typedef unsigned long long ull;

// ---------------- scratch ----------------
__device__ float g_h[(size_t)N_NODES * DIM];         // aggr + x  (gemm1 input)
__device__ float g_h1[(size_t)N_NODES * 256];        // h @ W1.T
__device__ float g_PQ[(size_t)N_NODES * 256];        // [P | Q] per node
__device__ float2 g_edge[(size_t)N_EDGES];           // sorted (src_as_float, ea)
__device__ int g_cnt[N_NODES];
__device__ int g_off[N_NODES];
__device__ int g_cur[N_NODES];
__device__ float g_bnsum[512];
__device__ float g_bnstat[512];
__device__ float g_W1T[128 * 256];                   // W1T[k][j]
__device__ float g_W2T[256 * 128];                   // W2T[k][j]
__device__ float g_WeT[256 * 128];                   // WeT0[kcat][j]

// ---------------- f32x2 helpers ----------------
__device__ __forceinline__ void fma2(ull& d, ull a, ull b) {
    asm("fma.rn.f32x2 %0, %1, %2, %0;" : "+l"(d) : "l"(a), "l"(b));
}
__device__ __forceinline__ ull pack_dup(float a) {
    ull r;
    asm("mov.b64 %0, {%1, %1};" : "=l"(r) : "f"(a));
    return r;
}
__device__ __forceinline__ float2 unpack2(ull v) {
    float2 f;
    f.x = __uint_as_float((unsigned)(v & 0xffffffffu));
    f.y = __uint_as_float((unsigned)(v >> 32));
    return f;
}
union W4U { float4 f; ull u[2]; };

// ---------------- weight transpose: in[J][K] -> out[K][J] ----------------
__global__ void __launch_bounds__(256) transp(const float* __restrict__ in, float* __restrict__ out,
                                              int J, int K)
{
    __shared__ float t[32][33];
    int bj = blockIdx.x * 32, bk = blockIdx.y * 32;
    int tx = threadIdx.x & 31, ty = threadIdx.x >> 5;
#pragma unroll
    for (int r = ty; r < 32; r += 8)
        t[r][tx] = in[(size_t)(bj + r) * K + bk + tx];
    __syncthreads();
#pragma unroll
    for (int r = ty; r < 32; r += 8)
        out[(size_t)(bk + r) * J + bj + tx] = t[tx][r];
}

// ---------------- edge sort: hist / scan / scatter ----------------
__global__ void __launch_bounds__(256) hist(const int* __restrict__ dst)
{
    int e = blockIdx.x * 256 + threadIdx.x;
    if (e < N_EDGES) atomicAdd(&g_cnt[dst[e]], 1);
}

__global__ void __launch_bounds__(1024) scan50k()
{
    __shared__ int wsum[32];
    __shared__ int sh_carry;
    int tid = threadIdx.x, lane = tid & 31, w = tid >> 5;
    if (tid == 0) sh_carry = 0;
    __syncthreads();
    for (int base = 0; base < N_NODES; base += 1024) {
        int i = base + tid;
        int v = (i < N_NODES) ? g_cnt[i] : 0;
        int x = v;
#pragma unroll
        for (int o = 1; o < 32; o <<= 1) { int y = __shfl_up_sync(~0u, x, o); if (lane >= o) x += y; }
        if (lane == 31) wsum[w] = x;
        __syncthreads();
        if (w == 0) {
            int s = wsum[lane];
#pragma unroll
            for (int o = 1; o < 32; o <<= 1) { int y = __shfl_up_sync(~0u, s, o); if (lane >= o) s += y; }
            wsum[lane] = s;
        }
        __syncthreads();
        int warp_excl = (w == 0) ? 0 : wsum[w - 1];
        int carry = sh_carry;
        int excl = carry + warp_excl + x - v;
        if (i < N_NODES) { g_off[i] = excl; g_cur[i] = excl; }
        __syncthreads();
        if (tid == 1023) sh_carry = carry + wsum[31];
        __syncthreads();
    }
}

__global__ void __launch_bounds__(256) scatter(
    const int* __restrict__ src, const int* __restrict__ dst, const float* __restrict__ ea)
{
    int e = blockIdx.x * 256 + threadIdx.x;
    if (e >= N_EDGES) return;
    int d = dst[e];
    int pos = atomicAdd(&g_cur[d], 1);
    g_edge[pos] = make_float2(__int_as_float(src[e]), ea[e]);
}

// ---------------- aggregate: warp per node -> g_h = softmax-aggr + x ----------------
__global__ void __launch_bounds__(256) aggregate(
    const float* __restrict__ x, const float* __restrict__ W_edge, const float* __restrict__ tptr)
{
    int gw = (blockIdx.x * 256 + threadIdx.x) >> 5;   // node
    int lane = threadIdx.x & 31;
    if (gw >= N_NODES) return;
    const float t = tptr[0];
    float4 w4 = *(const float4*)&W_edge[lane * 4];

    int beg = g_off[gw];
    int end = (gw == N_NODES - 1) ? N_EDGES : g_off[gw + 1];

    float4 aE = make_float4(0.f, 0.f, 0.f, 0.f);
    float4 aM = make_float4(0.f, 0.f, 0.f, 0.f);

    for (int b = beg; b < end; b += 32) {
        int j = b + lane;
        float2 ed = (j < end) ? g_edge[j] : make_float2(0.f, 0.f);
        int cnt = min(32, end - b);
        for (int q = 0; q < cnt; q++) {
            int s   = __shfl_sync(0xffffffffu, __float_as_int(ed.x), q);
            float a = __shfl_sync(0xffffffffu, ed.y, q);
            float4 xv = *(const float4*)&x[(size_t)s * DIM + lane * 4];
            float m0 = fmaxf(fmaf(a, w4.x, xv.x), 0.f) + 1e-7f;
            float m1 = fmaxf(fmaf(a, w4.y, xv.y), 0.f) + 1e-7f;
            float m2 = fmaxf(fmaf(a, w4.z, xv.z), 0.f) + 1e-7f;
            float m3 = fmaxf(fmaf(a, w4.w, xv.w), 0.f) + 1e-7f;
            float e0 = __expf(m0 * t), e1 = __expf(m1 * t);
            float e2 = __expf(m2 * t), e3 = __expf(m3 * t);
            aE.x += e0; aE.y += e1; aE.z += e2; aE.w += e3;
            aM.x = fmaf(m0, e0, aM.x); aM.y = fmaf(m1, e1, aM.y);
            aM.z = fmaf(m2, e2, aM.z); aM.w = fmaf(m3, e3, aM.w);
        }
    }
    float4 xn = *(const float4*)&x[(size_t)gw * DIM + lane * 4];
    float4 h;
    h.x = aM.x / (aE.x + 1e-16f) + xn.x;
    h.y = aM.y / (aE.y + 1e-16f) + xn.y;
    h.z = aM.z / (aE.z + 1e-16f) + xn.z;
    h.w = aM.w / (aE.w + 1e-16f) + xn.w;
    *(float4*)&g_h[(size_t)gw * DIM + lane * 4] = h;
}

// ============================================================================
// gemm1: g_h1 = g_h @ W1.T (out 256 cols) ; BN partial sums
// tile 64 rows x 256 cols, K=128, 256 threads, 8x8 per thread
// ============================================================================
#define G1SMEM ((128 * 260 + 128 * 68) * 4)
__global__ void __launch_bounds__(256) gemm1()
{
    extern __shared__ float sh[];
    float* Wsh  = sh;               // [k<128][j<256] stride 260
    float* hshT = sh + 128 * 260;   // [k<128][r<64]  stride 68
    int tid = threadIdx.x;
    int row0 = blockIdx.x * 64;

    for (int i = tid; i < 128 * 64; i += 256) {
        int k = i >> 6, j4 = (i & 63) << 2;
        *(float4*)&Wsh[k * 260 + j4] = *(const float4*)&g_W1T[k * 256 + j4];
    }
    for (int i = tid; i < 64 * 64; i += 256) {
        int r = i >> 6, k2 = (i & 63) << 1;
        int row = row0 + r;
        float2 hv = make_float2(0.f, 0.f);
        if (row < N_NODES) hv = *(const float2*)&g_h[(size_t)row * DIM + k2];
        hshT[k2 * 68 + r] = hv.x;
        hshT[(k2 + 1) * 68 + r] = hv.y;
    }
    __syncthreads();

    int tc = tid & 31, tr = tid >> 5;
    int j0 = tc * 8, r0 = tr * 8;
    ull acc[8][4];
#pragma unroll
    for (int i = 0; i < 8; i++)
#pragma unroll
        for (int jp = 0; jp < 4; jp++) acc[i][jp] = 0ull;

#pragma unroll 4
    for (int k = 0; k < 128; k++) {
        W4U wa, wb;
        wa.f = *(const float4*)&Wsh[k * 260 + j0];
        wb.f = *(const float4*)&Wsh[k * 260 + j0 + 4];
        float4 a0 = *(const float4*)&hshT[k * 68 + r0];
        float4 a1 = *(const float4*)&hshT[k * 68 + r0 + 4];
        float af[8] = {a0.x, a0.y, a0.z, a0.w, a1.x, a1.y, a1.z, a1.w};
#pragma unroll
        for (int i = 0; i < 8; i++) {
            ull A = pack_dup(af[i]);
            fma2(acc[i][0], A, wa.u[0]);
            fma2(acc[i][1], A, wa.u[1]);
            fma2(acc[i][2], A, wb.u[0]);
            fma2(acc[i][3], A, wb.u[1]);
        }
    }

    float cs[8], cq[8];
#pragma unroll
    for (int c = 0; c < 8; c++) { cs[c] = 0.f; cq[c] = 0.f; }
#pragma unroll
    for (int i = 0; i < 8; i++) {
        int row = row0 + r0 + i;
        if (row < N_NODES) {
            float2 p0 = unpack2(acc[i][0]);
            float2 p1 = unpack2(acc[i][1]);
            float2 p2 = unpack2(acc[i][2]);
            float2 p3 = unpack2(acc[i][3]);
            *(float4*)(g_h1 + (size_t)row * 256 + j0)     = make_float4(p0.x, p0.y, p1.x, p1.y);
            *(float4*)(g_h1 + (size_t)row * 256 + j0 + 4) = make_float4(p2.x, p2.y, p3.x, p3.y);
            float v[8] = {p0.x, p0.y, p1.x, p1.y, p2.x, p2.y, p3.x, p3.y};
#pragma unroll
            for (int c = 0; c < 8; c++) { cs[c] += v[c]; cq[c] += v[c] * v[c]; }
        }
    }
    __syncthreads();
    float* red = hshT;
#pragma unroll
    for (int c = 0; c < 8; c++) { red[tid * 16 + c] = cs[c]; red[tid * 16 + 8 + c] = cq[c]; }
    __syncthreads();
    {
        int c = tid;
        int tcq = c >> 3, jc = c & 7;
        float s = 0.f, q = 0.f;
#pragma unroll
        for (int trq = 0; trq < 8; trq++) {
            int idx = ((trq << 5) + tcq) * 16;
            s += red[idx + jc];
            q += red[idx + 8 + jc];
        }
        atomicAdd(&g_bnsum[c], s);
        atomicAdd(&g_bnsum[256 + c], q);
    }
}

// ---------------- bn stats finalize ----------------
__global__ void bn_stat(const float* __restrict__ bng, const float* __restrict__ bnb)
{
    int j = threadIdx.x;
    float s = g_bnsum[j], s2 = g_bnsum[256 + j];
    float mu = s * (1.0f / N_NODES);
    float var = s2 * (1.0f / N_NODES) - mu * mu;
    float rstd = rsqrtf(var + 1e-5f);
    float sc = rstd * bng[j];
    g_bnstat[j] = sc;
    g_bnstat[256 + j] = bnb[j] - mu * sc;
}

__device__ __forceinline__ float elu1(float v) { return v > 0.f ? v : expm1f(v); }

// ============================================================================
// gemm2: relu(bn(g_h1)) @ W2.T (out 128 cols, K=256 in 2 stages) -> LN -> ELU -> out_x
// ============================================================================
#define G2SMEM ((256 * 132 + 128 * 68) * 4)
__global__ void __launch_bounds__(256) gemm2(
    const float* __restrict__ lng, const float* __restrict__ lnb, float* __restrict__ out_x)
{
    extern __shared__ float sh[];
    float* Wsh  = sh;               // [k<256][j<128] stride 132
    float* hshT = sh + 256 * 132;   // [k<128][r<64]  stride 68
    int tid = threadIdx.x;
    int row0 = blockIdx.x * 64;

    for (int i = tid; i < 256 * 32; i += 256) {
        int k = i >> 5, j4 = (i & 31) << 2;
        *(float4*)&Wsh[k * 132 + j4] = *(const float4*)&g_W2T[k * 128 + j4];
    }

    int tc = tid & 31, tr = tid >> 5;
    int j0 = tc * 4, r0 = tr * 8;
    ull acc[8][2];
#pragma unroll
    for (int i = 0; i < 8; i++) { acc[i][0] = 0ull; acc[i][1] = 0ull; }

#pragma unroll
    for (int s = 0; s < 2; s++) {
        __syncthreads();
        for (int i = tid; i < 64 * 64; i += 256) {
            int r = i >> 6, k2 = (i & 63) << 1;
            int row = row0 + r;
            float v0 = 0.f, v1 = 0.f;
            if (row < N_NODES) {
                int kc = s * 128 + k2;
                float2 hv = *(const float2*)&g_h1[(size_t)row * 256 + kc];
                v0 = fmaxf(fmaf(hv.x, g_bnstat[kc],     g_bnstat[256 + kc]),     0.f);
                v1 = fmaxf(fmaf(hv.y, g_bnstat[kc + 1], g_bnstat[256 + kc + 1]), 0.f);
            }
            hshT[k2 * 68 + r] = v0;
            hshT[(k2 + 1) * 68 + r] = v1;
        }
        __syncthreads();

#pragma unroll 4
        for (int k = 0; k < 128; k++) {
            W4U w;
            w.f = *(const float4*)&Wsh[(s * 128 + k) * 132 + j0];
            float4 a0 = *(const float4*)&hshT[k * 68 + r0];
            float4 a1 = *(const float4*)&hshT[k * 68 + r0 + 4];
            float af[8] = {a0.x, a0.y, a0.z, a0.w, a1.x, a1.y, a1.z, a1.w};
#pragma unroll
            for (int i = 0; i < 8; i++) {
                ull A = pack_dup(af[i]);
                fma2(acc[i][0], A, w.u[0]);
                fma2(acc[i][1], A, w.u[1]);
            }
        }
    }

    float4 gv = *(const float4*)(lng + j0);
    float4 bv = *(const float4*)(lnb + j0);
#pragma unroll
    for (int i = 0; i < 8; i++) {
        int row = row0 + r0 + i;
        float2 p0 = unpack2(acc[i][0]);
        float2 p1 = unpack2(acc[i][1]);
        float s1 = p0.x + p0.y + p1.x + p1.y;
        float s2 = p0.x * p0.x + p0.y * p0.y + p1.x * p1.x + p1.y * p1.y;
#pragma unroll
        for (int o = 16; o > 0; o >>= 1) {
            s1 += __shfl_xor_sync(0xffffffffu, s1, o);
            s2 += __shfl_xor_sync(0xffffffffu, s2, o);
        }
        float mu = s1 * (1.f / 128.f);
        float var = s2 * (1.f / 128.f) - mu * mu;
        float rstd = rsqrtf(var + 1e-5f);
        if (row < N_NODES) {
            float4 o;
            o.x = elu1((p0.x - mu) * rstd * gv.x + bv.x);
            o.y = elu1((p0.y - mu) * rstd * gv.y + bv.y);
            o.z = elu1((p1.x - mu) * rstd * gv.z + bv.z);
            o.w = elu1((p1.y - mu) * rstd * gv.w + bv.w);
            *(float4*)(out_x + (size_t)row * DIM + j0) = o;
        }
    }
}

// ============================================================================
// gemm3: g_PQ = out_x @ [WeL | WeR].T (out 256 cols, K=128)
// ============================================================================
#define G3SMEM G1SMEM
__global__ void __launch_bounds__(256) gemm3(const float* __restrict__ out_x)
{
    extern __shared__ float sh[];
    float* Wsh  = sh;               // [k<128][jj<256] stride 260
    float* hshT = sh + 128 * 260;   // [k<128][r<64] stride 68
    int tid = threadIdx.x;
    int row0 = blockIdx.x * 64;

    for (int i = tid; i < 128 * 64; i += 256) {
        int k = i >> 6, j4 = (i & 63) << 2;
        const float* srcp = (j4 < 128) ? &g_WeT[k * 128 + j4]
                                       : &g_WeT[(128 + k) * 128 + (j4 - 128)];
        *(float4*)&Wsh[k * 260 + j4] = *(const float4*)srcp;
    }
    for (int i = tid; i < 64 * 64; i += 256) {
        int r = i >> 6, k2 = (i & 63) << 1;
        int row = row0 + r;
        float2 hv = make_float2(0.f, 0.f);
        if (row < N_NODES) hv = *(const float2*)&out_x[(size_t)row * DIM + k2];
        hshT[k2 * 68 + r] = hv.x;
        hshT[(k2 + 1) * 68 + r] = hv.y;
    }
    __syncthreads();

    int tc = tid & 31, tr = tid >> 5;
    int j0 = tc * 8, r0 = tr * 8;
    ull acc[8][4];
#pragma unroll
    for (int i = 0; i < 8; i++)
#pragma unroll
        for (int jp = 0; jp < 4; jp++) acc[i][jp] = 0ull;

#pragma unroll 4
    for (int k = 0; k < 128; k++) {
        W4U wa, wb;
        wa.f = *(const float4*)&Wsh[k * 260 + j0];
        wb.f = *(const float4*)&Wsh[k * 260 + j0 + 4];
        float4 a0 = *(const float4*)&hshT[k * 68 + r0];
        float4 a1 = *(const float4*)&hshT[k * 68 + r0 + 4];
        float af[8] = {a0.x, a0.y, a0.z, a0.w, a1.x, a1.y, a1.z, a1.w};
#pragma unroll
        for (int i = 0; i < 8; i++) {
            ull A = pack_dup(af[i]);
            fma2(acc[i][0], A, wa.u[0]);
            fma2(acc[i][1], A, wa.u[1]);
            fma2(acc[i][2], A, wb.u[0]);
            fma2(acc[i][3], A, wb.u[1]);
        }
    }
#pragma unroll
    for (int i = 0; i < 8; i++) {
        int row = row0 + r0 + i;
        if (row < N_NODES) {
            float2 p0 = unpack2(acc[i][0]);
            float2 p1 = unpack2(acc[i][1]);
            float2 p2 = unpack2(acc[i][2]);
            float2 p3 = unpack2(acc[i][3]);
            *(float4*)(g_PQ + (size_t)row * 256 + j0)     = make_float4(p0.x, p0.y, p1.x, p1.y);
            *(float4*)(g_PQ + (size_t)row * 256 + j0 + 4) = make_float4(p2.x, p2.y, p3.x, p3.y);
        }
    }
}

// ---------------- edge_out: per-edge P[src]+Q[dst]+be -> GELU -> LN -> out_e ----------------
__global__ void __launch_bounds__(256) edge_out(
    const int* __restrict__ src, const int* __restrict__ dst,
    const float* __restrict__ be, const float* __restrict__ lng, const float* __restrict__ lnb,
    float* __restrict__ out_e)
{
    int tid = threadIdx.x;
    int lane = tid & 31;
    int j0 = lane * 4;
    float4 bev = *(const float4*)(be + j0);
    float4 gv  = *(const float4*)(lng + j0);
    float4 bv  = *(const float4*)(lnb + j0);

    int e = blockIdx.x * 8 + (tid >> 5);
    if (e >= N_EDGES) return;
    int s = src[e], d = dst[e];

    float4 p = *(const float4*)(g_PQ + (size_t)s * 256 + j0);
    float4 q = *(const float4*)(g_PQ + (size_t)d * 256 + 128 + j0);
    float g0, g1, g2, g3;
    {
        float v0 = p.x + q.x + bev.x;
        float v1 = p.y + q.y + bev.y;
        float v2 = p.z + q.z + bev.z;
        float v3 = p.w + q.w + bev.w;
        g0 = 0.5f * v0 * (1.f + erff(v0 * 0.70710678118654752f));
        g1 = 0.5f * v1 * (1.f + erff(v1 * 0.70710678118654752f));
        g2 = 0.5f * v2 * (1.f + erff(v2 * 0.70710678118654752f));
        g3 = 0.5f * v3 * (1.f + erff(v3 * 0.70710678118654752f));
    }
    float s1 = g0 + g1 + g2 + g3;
    float s2 = g0 * g0 + g1 * g1 + g2 * g2 + g3 * g3;
#pragma unroll
    for (int o = 16; o > 0; o >>= 1) {
        s1 += __shfl_xor_sync(0xffffffffu, s1, o);
        s2 += __shfl_xor_sync(0xffffffffu, s2, o);
    }
    float mu = s1 * (1.f / 128.f);
    float var = s2 * (1.f / 128.f) - mu * mu;
    float rstd = rsqrtf(var + 1e-5f);
    float4 o;
    o.x = (g0 - mu) * rstd * gv.x + bv.x;
    o.y = (g1 - mu) * rstd * gv.y + bv.y;
    o.z = (g2 - mu) * rstd * gv.z + bv.z;
    o.w = (g3 - mu) * rstd * gv.w + bv.w;
    *(float4*)(out_e + (size_t)e * DIM + j0) = o;
}

// ---------------- launch ----------------
extern "C" void kernel_launch(void* const* d_in, const int* in_sizes, int n_in,
                              void* d_out, int out_size)
{
    const float* x      = (const float*)d_in[0];
    const int*   ei     = (const int*)  d_in[1];
    const float* ea     = (const float*)d_in[2];
    const float* W_edge = (const float*)d_in[3];
    const float* tptr   = (const float*)d_in[4];
    const float* W1     = (const float*)d_in[5];
    const float* bng    = (const float*)d_in[6];
    const float* bnb    = (const float*)d_in[7];
    const float* W2     = (const float*)d_in[8];
    const float* lng    = (const float*)d_in[9];
    const float* lnb    = (const float*)d_in[10];
    const float* We     = (const float*)d_in[11];
    const float* be     = (const float*)d_in[12];
    const float* lneg   = (const float*)d_in[13];
    const float* lneb   = (const float*)d_in[14];

    const int* src = ei;
    const int* dst = ei + N_EDGES;

    float* out_x = (float*)d_out;
    float* out_e = out_x + (size_t)N_NODES * DIM;

    void *cntp, *bnp, *w1tp, *w2tp, *wetp;
    cudaGetSymbolAddress(&cntp, g_cnt);
    cudaGetSymbolAddress(&bnp, g_bnsum);
    cudaGetSymbolAddress(&w1tp, g_W1T);
    cudaGetSymbolAddress(&w2tp, g_W2T);
    cudaGetSymbolAddress(&wetp, g_WeT);
    cudaMemsetAsync(cntp, 0, sizeof(int) * N_NODES, 0);
    cudaMemsetAsync(bnp, 0, sizeof(float) * 512, 0);

    cudaFuncSetAttribute(gemm1, cudaFuncAttributeMaxDynamicSharedMemorySize, G1SMEM);
    cudaFuncSetAttribute(gemm2, cudaFuncAttributeMaxDynamicSharedMemorySize, G2SMEM);
    cudaFuncSetAttribute(gemm3, cudaFuncAttributeMaxDynamicSharedMemorySize, G3SMEM);

    int eblocks256 = (N_EDGES + 255) / 256;
    int eblocks = (N_EDGES + 7) / 8;
    int nblocks = (N_NODES + 63) / 64;
    int ablocks = (N_NODES * 32 + 255) / 256;

    transp<<<dim3(8, 4), 256>>>(W1, (float*)w1tp, 256, 128);
    transp<<<dim3(4, 8), 256>>>(W2, (float*)w2tp, 128, 256);
    transp<<<dim3(4, 8), 256>>>(We, (float*)wetp, 128, 256);

    hist<<<eblocks256, 256>>>(dst);
    scan50k<<<1, 1024>>>();
    scatter<<<eblocks256, 256>>>(src, dst, ea);
    aggregate<<<ablocks, 256>>>(x, W_edge, tptr);

    gemm1<<<nblocks, 256, G1SMEM>>>();
    bn_stat<<<1, 256>>>(bng, bnb);
    gemm2<<<nblocks, 256, G2SMEM>>>(lng, lnb, out_x);
    gemm3<<<nblocks, 256, G3SMEM>>>(out_x);
    edge_out<<<eblocks, 256>>>(src, dst, be, lneg, lneb, out_e);
}

// round 6
// speedup vs baseline: 2.4867x; 1.3560x over previous
#include <cuda_runtime.h>
#include <cuda_bf16.h>
#include <math.h>
#include <stdint.h>

#define N_NODES 50000
#define N_EDGES 800000
#define DIM 128

typedef unsigned long long ull;
typedef unsigned short u16;

// ---------------- scratch ----------------
__device__ float g_h[(size_t)N_NODES * DIM];         // aggr + x  (gemm1 input)
__device__ float g_h1[(size_t)N_NODES * 256];        // h @ W1.T
__device__ float g_PQ[(size_t)N_NODES * 256];        // [P | Q] per node
__device__ float2 g_edge[(size_t)N_EDGES];           // sorted (src_as_float, ea)
__device__ int g_cnt[N_NODES];
__device__ int g_off[N_NODES];
__device__ int g_cur[N_NODES];
__device__ float g_bnsum[512];
__device__ float g_bnstat[512];
// pre-split bf16 weights, [k][n] layout, padded rows
__device__ __align__(16) u16 g_B1h[128 * 264], g_B1l[128 * 264];   // W1:  k<128, n<256, stride 264
__device__ __align__(16) u16 g_B3h[128 * 264], g_B3l[128 * 264];   // We-remap: k<128, n<256
__device__ __align__(16) u16 g_B2h[256 * 136], g_B2l[256 * 136];   // W2:  k<256, n<128, stride 136

// ---------------- mma helpers ----------------
__device__ __forceinline__ uint32_t smem_u32(const void* p) {
    uint32_t a;
    asm("{ .reg .u64 t; cvta.to.shared.u64 t, %1; cvt.u32.u64 %0, t; }" : "=r"(a) : "l"(p));
    return a;
}
__device__ __forceinline__ void ldmx4(uint32_t* r, uint32_t addr) {
    asm volatile("ldmatrix.sync.aligned.m8n8.x4.shared.b16 {%0,%1,%2,%3}, [%4];"
        : "=r"(r[0]), "=r"(r[1]), "=r"(r[2]), "=r"(r[3]) : "r"(addr));
}
__device__ __forceinline__ void ldmx4t(uint32_t* r, uint32_t addr) {
    asm volatile("ldmatrix.sync.aligned.m8n8.x4.trans.shared.b16 {%0,%1,%2,%3}, [%4];"
        : "=r"(r[0]), "=r"(r[1]), "=r"(r[2]), "=r"(r[3]) : "r"(addr));
}
__device__ __forceinline__ void mma16816(float* c, const uint32_t* a, uint32_t b0, uint32_t b1) {
    asm volatile("mma.sync.aligned.m16n8k16.row.col.f32.bf16.bf16.f32 "
        "{%0,%1,%2,%3}, {%4,%5,%6,%7}, {%8,%9}, {%0,%1,%2,%3};"
        : "+f"(c[0]), "+f"(c[1]), "+f"(c[2]), "+f"(c[3])
        : "r"(a[0]), "r"(a[1]), "r"(a[2]), "r"(a[3]), "r"(b0), "r"(b1));
}
__device__ __forceinline__ void split2(float a, float b, uint32_t& uh, uint32_t& ul) {
    __nv_bfloat16 h0 = __float2bfloat16_rn(a), h1 = __float2bfloat16_rn(b);
    float r0 = a - __bfloat162float(h0), r1 = b - __bfloat162float(h1);
    __nv_bfloat16 l0 = __float2bfloat16_rn(r0), l1 = __float2bfloat16_rn(r1);
    uh = (uint32_t)(*(u16*)&h0) | ((uint32_t)(*(u16*)&h1) << 16);
    ul = (uint32_t)(*(u16*)&l0) | ((uint32_t)(*(u16*)&l1) << 16);
}

// SMEM layout (bytes)
#define CTRL 4096
#define ASTR 272                       // A row stride: 128 bf16 + 8 pad
#define OFF_AH CTRL
#define OFF_AL (OFF_AH + 128 * ASTR)   // +34816
#define OFF_BH (OFF_AL + 128 * ASTR)
// tc256: B stride 528 (256 bf16 + 8 pad), 128 rows -> 67584 per term
#define SM_TC256 (OFF_BH + 2 * 67584)
// tc_mlp2: B stride 272, 256 rows -> 69632 per term
#define SM_MLP2  (OFF_BH + 2 * 69632)

// ---------------- weight prep: split + repack to [k][n] ----------------
__global__ void __launch_bounds__(256) prep_w256(
    const float* __restrict__ W, u16* __restrict__ Bh, u16* __restrict__ Bl, int mode)
{
    int i = blockIdx.x * 256 + threadIdx.x;
    if (i >= 256 * 128) return;
    int j = i >> 7, k = i & 127;
    float v = (mode == 0) ? W[j * 128 + k]
            : ((j < 128) ? W[j * 256 + k] : W[(j - 128) * 256 + 128 + k]);
    __nv_bfloat16 hb = __float2bfloat16_rn(v);
    float rr = v - __bfloat162float(hb);
    __nv_bfloat16 lb = __float2bfloat16_rn(rr);
    Bh[k * 264 + j] = *(u16*)&hb;
    Bl[k * 264 + j] = *(u16*)&lb;
}
__global__ void __launch_bounds__(256) prep_w2(const float* __restrict__ W)
{
    int i = blockIdx.x * 256 + threadIdx.x;
    if (i >= 128 * 256) return;
    int j = i >> 8, k = i & 255;
    float v = W[i];
    __nv_bfloat16 hb = __float2bfloat16_rn(v);
    float rr = v - __bfloat162float(hb);
    __nv_bfloat16 lb = __float2bfloat16_rn(rr);
    g_B2h[k * 136 + j] = *(u16*)&hb;
    g_B2l[k * 136 + j] = *(u16*)&lb;
}

// ---------------- edge sort: hist / scan / scatter ----------------
__global__ void __launch_bounds__(256) hist(const int* __restrict__ dst)
{
    int e = blockIdx.x * 256 + threadIdx.x;
    if (e < N_EDGES) atomicAdd(&g_cnt[dst[e]], 1);
}

__global__ void __launch_bounds__(1024) scan50k()
{
    __shared__ int wsum[32];
    __shared__ int sh_carry;
    int tid = threadIdx.x, lane = tid & 31, w = tid >> 5;
    if (tid == 0) sh_carry = 0;
    __syncthreads();
    for (int base = 0; base < N_NODES; base += 1024) {
        int i = base + tid;
        int v = (i < N_NODES) ? g_cnt[i] : 0;
        int x = v;
#pragma unroll
        for (int o = 1; o < 32; o <<= 1) { int y = __shfl_up_sync(~0u, x, o); if (lane >= o) x += y; }
        if (lane == 31) wsum[w] = x;
        __syncthreads();
        if (w == 0) {
            int s = wsum[lane];
#pragma unroll
            for (int o = 1; o < 32; o <<= 1) { int y = __shfl_up_sync(~0u, s, o); if (lane >= o) s += y; }
            wsum[lane] = s;
        }
        __syncthreads();
        int warp_excl = (w == 0) ? 0 : wsum[w - 1];
        int carry = sh_carry;
        int excl = carry + warp_excl + x - v;
        if (i < N_NODES) { g_off[i] = excl; g_cur[i] = excl; }
        __syncthreads();
        if (tid == 1023) sh_carry = carry + wsum[31];
        __syncthreads();
    }
}

__global__ void __launch_bounds__(256) scatter(
    const int* __restrict__ src, const int* __restrict__ dst, const float* __restrict__ ea)
{
    int e = blockIdx.x * 256 + threadIdx.x;
    if (e >= N_EDGES) return;
    int d = dst[e];
    int pos = atomicAdd(&g_cur[d], 1);
    g_edge[pos] = make_float2(__int_as_float(src[e]), ea[e]);
}

// ---------------- aggregate: warp per node -> g_h = softmax-aggr + x ----------------
__global__ void __launch_bounds__(256) aggregate(
    const float* __restrict__ x, const float* __restrict__ W_edge, const float* __restrict__ tptr)
{
    int gw = (blockIdx.x * 256 + threadIdx.x) >> 5;
    int lane = threadIdx.x & 31;
    if (gw >= N_NODES) return;
    const float t = tptr[0];
    float4 w4 = *(const float4*)&W_edge[lane * 4];

    int beg = g_off[gw];
    int end = (gw == N_NODES - 1) ? N_EDGES : g_off[gw + 1];

    float4 aE = make_float4(0.f, 0.f, 0.f, 0.f);
    float4 aM = make_float4(0.f, 0.f, 0.f, 0.f);

    for (int b = beg; b < end; b += 32) {
        int j = b + lane;
        float2 ed = (j < end) ? g_edge[j] : make_float2(0.f, 0.f);
        int cnt = min(32, end - b);
        for (int q = 0; q < cnt; q++) {
            int s   = __shfl_sync(0xffffffffu, __float_as_int(ed.x), q);
            float a = __shfl_sync(0xffffffffu, ed.y, q);
            float4 xv = *(const float4*)&x[(size_t)s * DIM + lane * 4];
            float m0 = fmaxf(fmaf(a, w4.x, xv.x), 0.f) + 1e-7f;
            float m1 = fmaxf(fmaf(a, w4.y, xv.y), 0.f) + 1e-7f;
            float m2 = fmaxf(fmaf(a, w4.z, xv.z), 0.f) + 1e-7f;
            float m3 = fmaxf(fmaf(a, w4.w, xv.w), 0.f) + 1e-7f;
            float e0 = __expf(m0 * t), e1 = __expf(m1 * t);
            float e2 = __expf(m2 * t), e3 = __expf(m3 * t);
            aE.x += e0; aE.y += e1; aE.z += e2; aE.w += e3;
            aM.x = fmaf(m0, e0, aM.x); aM.y = fmaf(m1, e1, aM.y);
            aM.z = fmaf(m2, e2, aM.z); aM.w = fmaf(m3, e3, aM.w);
        }
    }
    float4 xn = *(const float4*)&x[(size_t)gw * DIM + lane * 4];
    float4 h;
    h.x = aM.x / (aE.x + 1e-16f) + xn.x;
    h.y = aM.y / (aE.y + 1e-16f) + xn.y;
    h.z = aM.z / (aE.z + 1e-16f) + xn.z;
    h.w = aM.w / (aE.w + 1e-16f) + xn.w;
    *(float4*)&g_h[(size_t)gw * DIM + lane * 4] = h;
}

// ============================================================================
// tc256: out[rows x 256] = in[rows x 128] @ B[256 x 128]^T via mma.sync bf16 split
// 512 threads, tile 128 rows. warp w: rows (w&7)*16, col half (w>>3)*128
// ============================================================================
__global__ void __launch_bounds__(512, 1) tc256(
    const float* __restrict__ in, const u16* __restrict__ Bh, const u16* __restrict__ Bl,
    float* __restrict__ out)
{
    extern __shared__ __align__(16) char sm[];
    uint32_t sb = smem_u32(sm);
    int tid = threadIdx.x, wid = tid >> 5, lane = tid & 31;
    int row0 = blockIdx.x * 128;

    // B fill: flat copy, 67584 B each term (stride 528 matches global 264 u16)
    {
        const float4* bh = (const float4*)Bh;
        const float4* bl = (const float4*)Bl;
        float4* sh = (float4*)(sm + OFF_BH);
        float4* sl = (float4*)(sm + OFF_BH + 67584);
        for (int i = tid; i < 4224; i += 512) { sh[i] = bh[i]; sl[i] = bl[i]; }
    }
    // A fill: split fp32 -> bf16 hi/lo, [r][k] stride 272B
    for (int i = tid; i < 128 * 64; i += 512) {
        int r = i >> 6, k2 = (i & 63) << 1;
        int row = row0 + r;
        float2 hv = make_float2(0.f, 0.f);
        if (row < N_NODES) hv = *(const float2*)&in[(size_t)row * 128 + k2];
        uint32_t uh, ul;
        split2(hv.x, hv.y, uh, ul);
        *(uint32_t*)(sm + OFF_AH + r * ASTR + k2 * 2) = uh;
        *(uint32_t*)(sm + OFF_AL + r * ASTR + k2 * 2) = ul;
    }
    __syncthreads();

    int mrow0 = (wid & 7) * 16, nh = wid >> 3;
    uint32_t aRow = mrow0 + (lane & 7) + ((lane >> 3) & 1) * 8;
    uint32_t aAddrH = sb + OFF_AH + aRow * ASTR + (lane >> 4) * 16;
    uint32_t aAddrL = aAddrH + (OFF_AL - OFF_AH);
    uint32_t bLaneRow = (lane & 7) + ((lane >> 3) & 1) * 8;
    uint32_t bLaneN = ((lane >> 4) & 1) * 16 + nh * 256;   // n offset bytes

    float c[16][4];
#pragma unroll
    for (int t = 0; t < 16; t++)
#pragma unroll
        for (int q = 0; q < 4; q++) c[t][q] = 0.f;

#pragma unroll
    for (int kst = 0; kst < 8; kst++) {
        uint32_t ah[4], al[4];
        ldmx4(ah, aAddrH + kst * 32);
        ldmx4(al, aAddrL + kst * 32);
        uint32_t bAddr = sb + OFF_BH + (kst * 16 + bLaneRow) * 528 + bLaneN;
#pragma unroll
        for (int tp = 0; tp < 8; tp++) {
            uint32_t bh[4], bl[4];
            ldmx4t(bh, bAddr + tp * 32);
            ldmx4t(bl, bAddr + tp * 32 + 67584);
            mma16816(c[2 * tp],     ah, bh[0], bh[1]);
            mma16816(c[2 * tp],     al, bh[0], bh[1]);
            mma16816(c[2 * tp],     ah, bl[0], bl[1]);
            mma16816(c[2 * tp + 1], ah, bh[2], bh[3]);
            mma16816(c[2 * tp + 1], al, bh[2], bh[3]);
            mma16816(c[2 * tp + 1], ah, bl[2], bl[3]);
        }
    }

    int rbase = row0 + mrow0 + (lane >> 2);
    int cbase = nh * 128 + (lane & 3) * 2;
#pragma unroll
    for (int t = 0; t < 16; t++) {
        int n0 = cbase + t * 8;
        if (rbase < N_NODES)     *(float2*)&out[(size_t)rbase * 256 + n0]       = make_float2(c[t][0], c[t][1]);
        if (rbase + 8 < N_NODES) *(float2*)&out[(size_t)(rbase + 8) * 256 + n0] = make_float2(c[t][2], c[t][3]);
    }
}

// ---------------- bn column reduction over g_h1 ----------------
__global__ void __launch_bounds__(256) bn_reduce()
{
    int t = threadIdx.x;
    int r0 = blockIdx.x * 250, r1 = min(r0 + 250, N_NODES);
    float s = 0.f, q = 0.f;
    for (int row = r0; row < r1; row++) {
        float v = g_h1[(size_t)row * 256 + t];
        s += v; q += v * v;
    }
    atomicAdd(&g_bnsum[t], s);
    atomicAdd(&g_bnsum[256 + t], q);
}

__global__ void bn_stat(const float* __restrict__ bng, const float* __restrict__ bnb)
{
    int j = threadIdx.x;
    float s = g_bnsum[j], s2 = g_bnsum[256 + j];
    float mu = s * (1.0f / N_NODES);
    float var = s2 * (1.0f / N_NODES) - mu * mu;
    float rstd = rsqrtf(var + 1e-5f);
    float sc = rstd * bng[j];
    g_bnstat[j] = sc;
    g_bnstat[256 + j] = bnb[j] - mu * sc;
}

__device__ __forceinline__ float elu1(float v) { return v > 0.f ? v : expm1f(v); }

// ============================================================================
// tc_mlp2: out_x = ELU(LN(relu(bn(g_h1)) @ W2.T))
// K=256 (2 A passes), out 128 cols. warp w: rows (w&7)*16, col half (w>>3)*64
// ============================================================================
__global__ void __launch_bounds__(512, 1) tc_mlp2(
    const float* __restrict__ lng, const float* __restrict__ lnb, float* __restrict__ out_x)
{
    extern __shared__ __align__(16) char sm[];
    uint32_t sb = smem_u32(sm);
    int tid = threadIdx.x, wid = tid >> 5, lane = tid & 31;
    int row0 = blockIdx.x * 128;

    float* red  = (float*)sm;            // [128][4]
    float* lngs = (float*)(sm + 2048);
    float* lnbs = (float*)(sm + 2560);
    if (tid < 128) { lngs[tid] = lng[tid]; lnbs[tid] = lnb[tid]; }

    // B fill: 69632 B per term, flat
    {
        const float4* bh = (const float4*)g_B2h;
        const float4* bl = (const float4*)g_B2l;
        float4* sh = (float4*)(sm + OFF_BH);
        float4* sl = (float4*)(sm + OFF_BH + 69632);
        for (int i = tid; i < 4352; i += 512) { sh[i] = bh[i]; sl[i] = bl[i]; }
    }

    int mrow0 = (wid & 7) * 16, nh = wid >> 3;
    uint32_t aRow = mrow0 + (lane & 7) + ((lane >> 3) & 1) * 8;
    uint32_t aAddrH = sb + OFF_AH + aRow * ASTR + (lane >> 4) * 16;
    uint32_t aAddrL = aAddrH + (OFF_AL - OFF_AH);
    uint32_t bLaneRow = (lane & 7) + ((lane >> 3) & 1) * 8;
    uint32_t bLaneN = ((lane >> 4) & 1) * 16 + nh * 128;

    float c[8][4];
#pragma unroll
    for (int t = 0; t < 8; t++)
#pragma unroll
        for (int q = 0; q < 4; q++) c[t][q] = 0.f;

#pragma unroll
    for (int s = 0; s < 2; s++) {
        __syncthreads();
        for (int i = tid; i < 128 * 64; i += 512) {
            int r = i >> 6, k2 = (i & 63) << 1;
            int row = row0 + r;
            float v0 = 0.f, v1 = 0.f;
            if (row < N_NODES) {
                int kc = s * 128 + k2;
                float2 hv = *(const float2*)&g_h1[(size_t)row * 256 + kc];
                v0 = fmaxf(fmaf(hv.x, g_bnstat[kc],     g_bnstat[256 + kc]),     0.f);
                v1 = fmaxf(fmaf(hv.y, g_bnstat[kc + 1], g_bnstat[256 + kc + 1]), 0.f);
            }
            uint32_t uh, ul;
            split2(v0, v1, uh, ul);
            *(uint32_t*)(sm + OFF_AH + r * ASTR + k2 * 2) = uh;
            *(uint32_t*)(sm + OFF_AL + r * ASTR + k2 * 2) = ul;
        }
        __syncthreads();

#pragma unroll
        for (int kst = 0; kst < 8; kst++) {
            uint32_t ah[4], al[4];
            ldmx4(ah, aAddrH + kst * 32);
            ldmx4(al, aAddrL + kst * 32);
            uint32_t bAddr = sb + OFF_BH + (s * 128 + kst * 16 + bLaneRow) * 272 + bLaneN;
#pragma unroll
            for (int tp = 0; tp < 4; tp++) {
                uint32_t bh[4], bl[4];
                ldmx4t(bh, bAddr + tp * 32);
                ldmx4t(bl, bAddr + tp * 32 + 69632);
                mma16816(c[2 * tp],     ah, bh[0], bh[1]);
                mma16816(c[2 * tp],     al, bh[0], bh[1]);
                mma16816(c[2 * tp],     ah, bl[0], bl[1]);
                mma16816(c[2 * tp + 1], ah, bh[2], bh[3]);
                mma16816(c[2 * tp + 1], al, bh[2], bh[3]);
                mma16816(c[2 * tp + 1], ah, bl[2], bl[3]);
            }
        }
    }

    // LN + ELU epilogue
    float s1a = 0.f, s2a = 0.f, s1b = 0.f, s2b = 0.f;
#pragma unroll
    for (int t = 0; t < 8; t++) {
        s1a += c[t][0] + c[t][1];
        s2a += c[t][0] * c[t][0] + c[t][1] * c[t][1];
        s1b += c[t][2] + c[t][3];
        s2b += c[t][2] * c[t][2] + c[t][3] * c[t][3];
    }
#pragma unroll
    for (int o = 1; o < 4; o <<= 1) {
        s1a += __shfl_xor_sync(~0u, s1a, o);
        s2a += __shfl_xor_sync(~0u, s2a, o);
        s1b += __shfl_xor_sync(~0u, s1b, o);
        s2b += __shfl_xor_sync(~0u, s2b, o);
    }
    __syncthreads();
    if ((lane & 3) == 0) {
        int r = mrow0 + (lane >> 2);
        red[r * 4 + nh * 2]           = s1a;
        red[r * 4 + nh * 2 + 1]       = s2a;
        red[(r + 8) * 4 + nh * 2]     = s1b;
        red[(r + 8) * 4 + nh * 2 + 1] = s2b;
    }
    __syncthreads();
    {
        int ra = mrow0 + (lane >> 2), rb = ra + 8;
        float mua = (red[ra * 4] + red[ra * 4 + 2]) * (1.f / 128.f);
        float vara = (red[ra * 4 + 1] + red[ra * 4 + 3]) * (1.f / 128.f) - mua * mua;
        float rsa = rsqrtf(vara + 1e-5f);
        float mub = (red[rb * 4] + red[rb * 4 + 2]) * (1.f / 128.f);
        float varb = (red[rb * 4 + 1] + red[rb * 4 + 3]) * (1.f / 128.f) - mub * mub;
        float rsb = rsqrtf(varb + 1e-5f);
        int rowa = row0 + ra, rowb = row0 + rb;
#pragma unroll
        for (int t = 0; t < 8; t++) {
            int col = nh * 64 + t * 8 + (lane & 3) * 2;
            if (rowa < N_NODES) {
                float2 o;
                o.x = elu1((c[t][0] - mua) * rsa * lngs[col]     + lnbs[col]);
                o.y = elu1((c[t][1] - mua) * rsa * lngs[col + 1] + lnbs[col + 1]);
                *(float2*)&out_x[(size_t)rowa * DIM + col] = o;
            }
            if (rowb < N_NODES) {
                float2 o;
                o.x = elu1((c[t][2] - mub) * rsb * lngs[col]     + lnbs[col]);
                o.y = elu1((c[t][3] - mub) * rsb * lngs[col + 1] + lnbs[col + 1]);
                *(float2*)&out_x[(size_t)rowb * DIM + col] = o;
            }
        }
    }
}

// ---------------- edge_out ----------------
__global__ void __launch_bounds__(256) edge_out(
    const int* __restrict__ src, const int* __restrict__ dst,
    const float* __restrict__ be, const float* __restrict__ lng, const float* __restrict__ lnb,
    float* __restrict__ out_e)
{
    int tid = threadIdx.x;
    int lane = tid & 31;
    int j0 = lane * 4;
    float4 bev = *(const float4*)(be + j0);
    float4 gv  = *(const float4*)(lng + j0);
    float4 bv  = *(const float4*)(lnb + j0);

    int e = blockIdx.x * 8 + (tid >> 5);
    if (e >= N_EDGES) return;
    int s = src[e], d = dst[e];

    float4 p = *(const float4*)(g_PQ + (size_t)s * 256 + j0);
    float4 q = *(const float4*)(g_PQ + (size_t)d * 256 + 128 + j0);
    float g0, g1, g2, g3;
    {
        float v0 = p.x + q.x + bev.x;
        float v1 = p.y + q.y + bev.y;
        float v2 = p.z + q.z + bev.z;
        float v3 = p.w + q.w + bev.w;
        g0 = 0.5f * v0 * (1.f + erff(v0 * 0.70710678118654752f));
        g1 = 0.5f * v1 * (1.f + erff(v1 * 0.70710678118654752f));
        g2 = 0.5f * v2 * (1.f + erff(v2 * 0.70710678118654752f));
        g3 = 0.5f * v3 * (1.f + erff(v3 * 0.70710678118654752f));
    }
    float s1 = g0 + g1 + g2 + g3;
    float s2 = g0 * g0 + g1 * g1 + g2 * g2 + g3 * g3;
#pragma unroll
    for (int o = 16; o > 0; o >>= 1) {
        s1 += __shfl_xor_sync(0xffffffffu, s1, o);
        s2 += __shfl_xor_sync(0xffffffffu, s2, o);
    }
    float mu = s1 * (1.f / 128.f);
    float var = s2 * (1.f / 128.f) - mu * mu;
    float rstd = rsqrtf(var + 1e-5f);
    float4 o;
    o.x = (g0 - mu) * rstd * gv.x + bv.x;
    o.y = (g1 - mu) * rstd * gv.y + bv.y;
    o.z = (g2 - mu) * rstd * gv.z + bv.z;
    o.w = (g3 - mu) * rstd * gv.w + bv.w;
    *(float4*)(out_e + (size_t)e * DIM + j0) = o;
}

// ---------------- launch ----------------
extern "C" void kernel_launch(void* const* d_in, const int* in_sizes, int n_in,
                              void* d_out, int out_size)
{
    const float* x      = (const float*)d_in[0];
    const int*   ei     = (const int*)  d_in[1];
    const float* ea     = (const float*)d_in[2];
    const float* W_edge = (const float*)d_in[3];
    const float* tptr   = (const float*)d_in[4];
    const float* W1     = (const float*)d_in[5];
    const float* bng    = (const float*)d_in[6];
    const float* bnb    = (const float*)d_in[7];
    const float* W2     = (const float*)d_in[8];
    const float* lng    = (const float*)d_in[9];
    const float* lnb    = (const float*)d_in[10];
    const float* We     = (const float*)d_in[11];
    const float* be     = (const float*)d_in[12];
    const float* lneg   = (const float*)d_in[13];
    const float* lneb   = (const float*)d_in[14];

    const int* src = ei;
    const int* dst = ei + N_EDGES;

    float* out_x = (float*)d_out;
    float* out_e = out_x + (size_t)N_NODES * DIM;

    void *cntp, *bnp, *b1h, *b1l, *b3h, *b3l, *ghp, *h1p, *pqp;
    cudaGetSymbolAddress(&cntp, g_cnt);
    cudaGetSymbolAddress(&bnp, g_bnsum);
    cudaGetSymbolAddress(&b1h, g_B1h); cudaGetSymbolAddress(&b1l, g_B1l);
    cudaGetSymbolAddress(&b3h, g_B3h); cudaGetSymbolAddress(&b3l, g_B3l);
    cudaGetSymbolAddress(&ghp, g_h);
    cudaGetSymbolAddress(&h1p, g_h1);
    cudaGetSymbolAddress(&pqp, g_PQ);
    cudaMemsetAsync(cntp, 0, sizeof(int) * N_NODES, 0);
    cudaMemsetAsync(bnp, 0, sizeof(float) * 512, 0);

    cudaFuncSetAttribute(tc256, cudaFuncAttributeMaxDynamicSharedMemorySize, SM_TC256);
    cudaFuncSetAttribute(tc_mlp2, cudaFuncAttributeMaxDynamicSharedMemorySize, SM_MLP2);

    int eblocks256 = (N_EDGES + 255) / 256;
    int eblocks = (N_EDGES + 7) / 8;
    int ablocks = (N_NODES * 32 + 255) / 256;
    int tblocks = (N_NODES + 127) / 128;

    prep_w256<<<128, 256>>>(W1, (u16*)b1h, (u16*)b1l, 0);
    prep_w256<<<128, 256>>>(We, (u16*)b3h, (u16*)b3l, 1);
    prep_w2<<<128, 256>>>(W2);

    hist<<<eblocks256, 256>>>(dst);
    scan50k<<<1, 1024>>>();
    scatter<<<eblocks256, 256>>>(src, dst, ea);
    aggregate<<<ablocks, 256>>>(x, W_edge, tptr);

    tc256<<<tblocks, 512, SM_TC256>>>((const float*)ghp, (const u16*)b1h, (const u16*)b1l, (float*)h1p);
    bn_reduce<<<200, 256>>>();
    bn_stat<<<1, 256>>>(bng, bnb);
    tc_mlp2<<<tblocks, 512, SM_MLP2>>>(lng, lnb, out_x);
    tc256<<<tblocks, 512, SM_TC256>>>(out_x, (const u16*)b3h, (const u16*)b3l, (float*)pqp);
    edge_out<<<eblocks, 256>>>(src, dst, be, lneg, lneb, out_e);
}